// round 1
// baseline (speedup 1.0000x reference)
#include <cuda_runtime.h>
#include <cstdint>

// ---------------------------------------------------------------------------
// HydraAttention_v2 — fp32 baseline
// B=8, C=64, H=W=256, N=65536, kc=vc=64
//
// Pipeline:
//  k_zero    : zero accumulators
//  k_twt     : transpose conv weights [O,I,3,3] -> [I, tap, O]
//  k_qkv     : per-pixel Q/K/V (1x1 conv), L2-norm Q,K; write Qn; block-partial
//              ksum/vsum/agg_kv with atomics
//  k_fin     : per batch: wrvs[o] = Wr·vsum ; M2[m][o] = sum_c Wr[o,c]*agg[m,c]
//  k_attn    : attn[o,n] = br[o] + denom_n * (wrvs[o] + sum_m M2[m,o]*qn[m,n])
//  k_conv x2 : 3x3 SAME convs; second fuses *x + x residual
// ---------------------------------------------------------------------------

#define BATCH 8
#define CH    64
#define NPIX  65536

// scratch (device globals; no allocations allowed)
__device__ float g_Qn[BATCH * CH * NPIX];
__device__ float g_attn[BATCH * CH * NPIX];
__device__ float g_t1[BATCH * CH * NPIX];
__device__ float g_ksum[BATCH * CH];
__device__ float g_vsum[BATCH * CH];
__device__ float g_aggkv[BATCH * CH * CH];   // [b][m][c]
__device__ float g_M2[BATCH * CH * CH];      // [b][m][o]
__device__ float g_wrvs[BATCH * CH];
__device__ float g_wt1[CH * 9 * CH];         // [i][tap][o]
__device__ float g_wt2[CH * 9 * CH];

// ---------------------------------------------------------------------------
__global__ void k_zero() {
    int i = blockIdx.x * 256 + threadIdx.x;
    if (i < BATCH * CH) { g_ksum[i] = 0.f; g_vsum[i] = 0.f; }
    if (i < BATCH * CH * CH) g_aggkv[i] = 0.f;
}

__global__ void k_twt(const float* __restrict__ W1, const float* __restrict__ W2) {
    int d = blockIdx.x * 256 + threadIdx.x;
    if (d >= 2 * CH * 9 * CH) return;
    const float* W = (d < CH * 9 * CH) ? W1 : W2;
    float* dst = (d < CH * 9 * CH) ? g_wt1 : g_wt2;
    int e = d % (CH * 9 * CH);
    int o = e & 63;
    int kk = (e >> 6) % 9;
    int i = e / (64 * 9);
    dst[e] = W[(o * 64 + i) * 9 + kk];    // W[o][i][ky][kx]
}

// ---------------------------------------------------------------------------
// 64x64 matvec, weights transposed in smem with stride 68 (conflict-free fp4)
__device__ __forceinline__ void matvec64(const float* __restrict__ ws,
                                         const float* __restrict__ bias,
                                         const float* __restrict__ xp,
                                         float acc[64]) {
#pragma unroll
    for (int o4 = 0; o4 < 16; o4++) {
        float4 bb = __ldg(((const float4*)bias) + o4);
        acc[4 * o4 + 0] = bb.x; acc[4 * o4 + 1] = bb.y;
        acc[4 * o4 + 2] = bb.z; acc[4 * o4 + 3] = bb.w;
    }
#pragma unroll 4
    for (int c = 0; c < 64; c++) {
        float xc = __ldg(xp + ((size_t)c << 16));
        const float4* w4 = (const float4*)(ws + c * 68);
#pragma unroll
        for (int o4 = 0; o4 < 16; o4++) {
            float4 w = w4[o4];
            acc[4 * o4 + 0] += w.x * xc;
            acc[4 * o4 + 1] += w.y * xc;
            acc[4 * o4 + 2] += w.z * xc;
            acc[4 * o4 + 3] += w.w * xc;
        }
    }
}

// smem: 3*64*68 (wq,wk,wv transposed) + 2*64*256 (kn, v tiles) floats
#define SMEM_QKV ((3 * 64 * 68 + 2 * 64 * 256) * 4)

__global__ void __launch_bounds__(256, 1)
k_qkv(const float* __restrict__ x,
      const float* __restrict__ Wq, const float* __restrict__ bq,
      const float* __restrict__ Wk, const float* __restrict__ bk,
      const float* __restrict__ Wv, const float* __restrict__ bv) {
    extern __shared__ float sm[];
    float* wq_s = sm;
    float* wk_s = sm + 64 * 68;
    float* wv_s = sm + 2 * 64 * 68;
    float* k_s  = sm + 3 * 64 * 68;
    float* v_s  = k_s + 64 * 256;

    const int tid = threadIdx.x;
    const int b = blockIdx.x >> 8;
    const int n = ((blockIdx.x & 255) << 8) + tid;

    // stage transposed weights (stride 68 to avoid write conflicts + keep fp4 align)
    for (int idx = tid; idx < 4096; idx += 256) {
        int o = idx >> 6, c = idx & 63;
        wq_s[c * 68 + o] = Wq[idx];
        wk_s[c * 68 + o] = Wk[idx];
        wv_s[c * 68 + o] = Wv[idx];
    }
    __syncthreads();

    const float* xp = x + ((size_t)b << 22) + n;
    float acc[64];

    // ---- Q (normalized) ----
    matvec64(wq_s, bq, xp, acc);
    float ss = 0.f;
#pragma unroll
    for (int o = 0; o < 64; o++) ss += acc[o] * acc[o];
    float inv = rsqrtf(ss);
#pragma unroll
    for (int o = 0; o < 64; o++)
        g_Qn[(((size_t)b * 64 + o) << 16) + n] = acc[o] * inv;

    // ---- K (normalized, to smem) ----
    matvec64(wk_s, bk, xp, acc);
    ss = 0.f;
#pragma unroll
    for (int o = 0; o < 64; o++) ss += acc[o] * acc[o];
    inv = rsqrtf(ss);
#pragma unroll
    for (int o = 0; o < 64; o++) k_s[o * 256 + tid] = acc[o] * inv;

    // ---- V (to smem) ----
    matvec64(wv_s, bv, xp, acc);
#pragma unroll
    for (int o = 0; o < 64; o++) v_s[o * 256 + tid] = acc[o];

    __syncthreads();

    // row sums -> ksum / vsum (skewed to avoid bank conflicts)
    if (tid < 128) {
        int row = tid & 63;
        const float* src = (tid < 64) ? k_s : v_s;
        float s = 0.f;
        for (int i = 0; i < 256; i++) {
            int p = (i + tid) & 255;
            s += src[row * 256 + p];
        }
        float* dstp = (tid < 64) ? &g_ksum[b * 64 + row] : &g_vsum[b * 64 + row];
        atomicAdd(dstp, s);
    }

    // agg_kv[m][c] partial: 4x4 register blocking per thread, skewed p
    const int m0 = (tid >> 4) << 2;
    const int c0 = (tid & 15) << 2;
    float a[4][4];
#pragma unroll
    for (int i = 0; i < 4; i++)
#pragma unroll
        for (int j = 0; j < 4; j++) a[i][j] = 0.f;

    for (int it = 0; it < 256; it++) {
        int p = (it + tid) & 255;
        float kv0 = k_s[(m0 + 0) * 256 + p];
        float kv1 = k_s[(m0 + 1) * 256 + p];
        float kv2 = k_s[(m0 + 2) * 256 + p];
        float kv3 = k_s[(m0 + 3) * 256 + p];
        float vv0 = v_s[(c0 + 0) * 256 + p];
        float vv1 = v_s[(c0 + 1) * 256 + p];
        float vv2 = v_s[(c0 + 2) * 256 + p];
        float vv3 = v_s[(c0 + 3) * 256 + p];
        a[0][0] += kv0 * vv0; a[0][1] += kv0 * vv1; a[0][2] += kv0 * vv2; a[0][3] += kv0 * vv3;
        a[1][0] += kv1 * vv0; a[1][1] += kv1 * vv1; a[1][2] += kv1 * vv2; a[1][3] += kv1 * vv3;
        a[2][0] += kv2 * vv0; a[2][1] += kv2 * vv1; a[2][2] += kv2 * vv2; a[2][3] += kv2 * vv3;
        a[3][0] += kv3 * vv0; a[3][1] += kv3 * vv1; a[3][2] += kv3 * vv2; a[3][3] += kv3 * vv3;
    }
#pragma unroll
    for (int i = 0; i < 4; i++)
#pragma unroll
        for (int j = 0; j < 4; j++)
            atomicAdd(&g_aggkv[((size_t)b * 64 + m0 + i) * 64 + c0 + j], a[i][j]);
}

// ---------------------------------------------------------------------------
__global__ void k_fin(const float* __restrict__ Wr) {
    int b = blockIdx.x, o = threadIdx.x;
    float wr[64];
#pragma unroll
    for (int c = 0; c < 64; c++) wr[c] = Wr[o * 64 + c];
    float s = 0.f;
#pragma unroll
    for (int c = 0; c < 64; c++) s += wr[c] * g_vsum[b * 64 + c];
    g_wrvs[b * 64 + o] = s;
    for (int m = 0; m < 64; m++) {
        float t = 0.f;
#pragma unroll
        for (int c = 0; c < 64; c++) t += wr[c] * g_aggkv[(b * 64 + m) * 64 + c];
        g_M2[(b * 64 + m) * 64 + o] = t;
    }
}

// ---------------------------------------------------------------------------
#define SMEM_ATTN ((64 * 64 + 64 * 256 + 64 + 64) * 4)

__global__ void __launch_bounds__(256, 1)
k_attn(const float* __restrict__ br) {
    extern __shared__ float sm[];
    float* m2_s = sm;                 // [m][o] : 4096
    float* q_s  = sm + 4096;          // [m][pixel] : 64*256
    float* ks_s = q_s + 64 * 256;     // 64
    float* wv_s = ks_s + 64;          // 64

    const int tid = threadIdx.x;
    const int b = blockIdx.x >> 8;
    const int n = ((blockIdx.x & 255) << 8) + tid;

    for (int idx = tid; idx < 4096; idx += 256) m2_s[idx] = g_M2[b * 4096 + idx];
    if (tid < 64) {
        ks_s[tid] = g_ksum[b * 64 + tid] + 1e-6f;
        wv_s[tid] = g_wrvs[b * 64 + tid];
    }
#pragma unroll 1
    for (int m = 0; m < 64; m++)
        q_s[m * 256 + tid] = g_Qn[(((size_t)b * 64 + m) << 16) + n];
    __syncthreads();

    float dot = 0.f;
#pragma unroll 4
    for (int m = 0; m < 64; m++) dot += q_s[m * 256 + tid] * ks_s[m];
    float denom = 1.f / (65536.f + dot);

    float acc[64];
#pragma unroll
    for (int o4 = 0; o4 < 16; o4++) {
        float4 w = ((const float4*)wv_s)[o4];
        acc[4 * o4 + 0] = w.x; acc[4 * o4 + 1] = w.y;
        acc[4 * o4 + 2] = w.z; acc[4 * o4 + 3] = w.w;
    }
#pragma unroll 4
    for (int m = 0; m < 64; m++) {
        float qm = q_s[m * 256 + tid];
        const float4* w4 = (const float4*)(m2_s + m * 64);
#pragma unroll
        for (int o4 = 0; o4 < 16; o4++) {
            float4 w = w4[o4];
            acc[4 * o4 + 0] += w.x * qm;
            acc[4 * o4 + 1] += w.y * qm;
            acc[4 * o4 + 2] += w.z * qm;
            acc[4 * o4 + 3] += w.w * qm;
        }
    }
#pragma unroll
    for (int o = 0; o < 64; o++)
        g_attn[(((size_t)b * 64 + o) << 16) + n] = acc[o] * denom + __ldg(&br[o]);
}

// ---------------------------------------------------------------------------
// 3x3 SAME conv, 64->64 channels. Tile 32x16 pixels, 512 threads.
// smem: input tile with halo [64][18][34] + weight chunk [16][9][64]
#define SMEM_CONV ((64 * 612 + 16 * 9 * 64) * 4)

__global__ void __launch_bounds__(512, 1)
k_conv(const float* __restrict__ src, const float* __restrict__ wt,
       const float* __restrict__ bias, float* __restrict__ dst,
       const float* __restrict__ xres, int fuse) {
    extern __shared__ float sm[];
    float* in_s = sm;                 // 64 * 612
    float* w_s  = sm + 64 * 612;      // 9216

    const int tid = threadIdx.x;
    const int bx = blockIdx.x & 7;
    const int by = (blockIdx.x >> 3) & 15;
    const int b  = blockIdx.x >> 7;
    const int tx0 = bx << 5, ty0 = by << 4;

    const float* sb = src + ((size_t)b << 22);

    // stage input tile (halo, zero-padded)
    for (int idx = tid; idx < 64 * 612; idx += 512) {
        int i = idx / 612;
        int r = idx % 612;
        int yy = r / 34, xx = r % 34;
        int gy = ty0 + yy - 1, gx = tx0 + xx - 1;
        float v = 0.f;
        if ((unsigned)gy < 256u && (unsigned)gx < 256u)
            v = sb[((size_t)i << 16) + (gy << 8) + gx];
        in_s[idx] = v;
    }

    const int lx = tid & 31, ly = tid >> 5;

    float acc[64];
#pragma unroll
    for (int o4 = 0; o4 < 16; o4++) {
        float4 bb = __ldg(((const float4*)bias) + o4);
        acc[4 * o4 + 0] = bb.x; acc[4 * o4 + 1] = bb.y;
        acc[4 * o4 + 2] = bb.z; acc[4 * o4 + 3] = bb.w;
    }

    for (int ch = 0; ch < 4; ch++) {
        __syncthreads();   // covers input staging (ch=0) and w_s reuse
        for (int idx = tid; idx < 9216; idx += 512)
            w_s[idx] = wt[ch * 9216 + idx];
        __syncthreads();
#pragma unroll 1
        for (int ii = 0; ii < 16; ii++) {
            const float* ibase = in_s + (ch * 16 + ii) * 612 + ly * 34 + lx;
            float xin[9];
#pragma unroll
            for (int ky = 0; ky < 3; ky++)
#pragma unroll
                for (int kx = 0; kx < 3; kx++)
                    xin[ky * 3 + kx] = ibase[ky * 34 + kx];
            const float4* wb = (const float4*)(w_s + ii * 9 * 64);
#pragma unroll
            for (int kk = 0; kk < 9; kk++) {
                float xv2 = xin[kk];
#pragma unroll
                for (int o4 = 0; o4 < 16; o4++) {
                    float4 w = wb[kk * 16 + o4];
                    acc[4 * o4 + 0] += w.x * xv2;
                    acc[4 * o4 + 1] += w.y * xv2;
                    acc[4 * o4 + 2] += w.z * xv2;
                    acc[4 * o4 + 3] += w.w * xv2;
                }
            }
        }
    }

    const int gy = ty0 + ly, gx = tx0 + lx;
    const size_t base = ((size_t)b << 22) + (gy << 8) + gx;
    if (fuse) {
#pragma unroll
        for (int o = 0; o < 64; o++) {
            float xv2 = xres[base + ((size_t)o << 16)];
            dst[base + ((size_t)o << 16)] = acc[o] * xv2 + xv2;
        }
    } else {
#pragma unroll
        for (int o = 0; o < 64; o++)
            dst[base + ((size_t)o << 16)] = acc[o];
    }
}

// ---------------------------------------------------------------------------
extern "C" void kernel_launch(void* const* d_in, const int* in_sizes, int n_in,
                              void* d_out, int out_size) {
    const float* x  = (const float*)d_in[0];
    const float* Wq = (const float*)d_in[1];
    const float* bq = (const float*)d_in[2];
    const float* Wk = (const float*)d_in[3];
    const float* bk = (const float*)d_in[4];
    const float* Wv = (const float*)d_in[5];
    const float* bv = (const float*)d_in[6];
    const float* Wr = (const float*)d_in[7];
    const float* br = (const float*)d_in[8];
    const float* W1 = (const float*)d_in[9];
    const float* b1 = (const float*)d_in[10];
    const float* W2 = (const float*)d_in[11];
    const float* b2 = (const float*)d_in[12];
    float* out = (float*)d_out;

    cudaFuncSetAttribute(k_qkv,  cudaFuncAttributeMaxDynamicSharedMemorySize, SMEM_QKV);
    cudaFuncSetAttribute(k_attn, cudaFuncAttributeMaxDynamicSharedMemorySize, SMEM_ATTN);
    cudaFuncSetAttribute(k_conv, cudaFuncAttributeMaxDynamicSharedMemorySize, SMEM_CONV);

    void *p_attn, *p_t1, *p_wt1, *p_wt2;
    cudaGetSymbolAddress(&p_attn, g_attn);
    cudaGetSymbolAddress(&p_t1, g_t1);
    cudaGetSymbolAddress(&p_wt1, g_wt1);
    cudaGetSymbolAddress(&p_wt2, g_wt2);

    k_zero<<<128, 256>>>();
    k_twt<<<288, 256>>>(W1, W2);
    k_qkv<<<2048, 256, SMEM_QKV>>>(x, Wq, bq, Wk, bk, Wv, bv);
    k_fin<<<8, 64>>>(Wr);
    k_attn<<<2048, 256, SMEM_ATTN>>>(br);
    k_conv<<<1024, 512, SMEM_CONV>>>((const float*)p_attn, (const float*)p_wt1,
                                     b1, (float*)p_t1, nullptr, 0);
    k_conv<<<1024, 512, SMEM_CONV>>>((const float*)p_t1, (const float*)p_wt2,
                                     b2, out, x, 1);
}

// round 2
// speedup vs baseline: 1.3770x; 1.3770x over previous
#include <cuda_runtime.h>
#include <cstdint>

// ---------------------------------------------------------------------------
// HydraAttention_v2 — fp32 with packed f32x2 FFMA (sm_103a FFMA2)
// B=8, C=64, H=W=256, N=65536, kc=vc=64
// ---------------------------------------------------------------------------

#define BATCH 8
#define CH    64
#define NPIX  65536

typedef unsigned long long ull;

__device__ float g_Qn[BATCH * CH * NPIX];
__device__ float g_attn[BATCH * CH * NPIX];
__device__ float g_t1[BATCH * CH * NPIX];
__device__ float g_ksum[BATCH * CH];
__device__ float g_vsum[BATCH * CH];
__device__ float g_aggkv[BATCH * CH * CH];   // [b][m][c]
__device__ float g_M2[BATCH * CH * CH];      // [b][m][o]
__device__ float g_wrvs[BATCH * CH];
__device__ float g_wt1[CH * 9 * CH];         // [i][tap][o]
__device__ float g_wt2[CH * 9 * CH];

// ---- packed fp32 helpers ---------------------------------------------------
__device__ __forceinline__ ull bcast2(float v) {
    ull r;
    asm("mov.b64 %0, {%1, %1};" : "=l"(r) : "f"(v));
    return r;
}
__device__ __forceinline__ void fma2(ull& d, ull a, ull b) {
    asm("fma.rn.f32x2 %0, %1, %2, %0;" : "+l"(d) : "l"(a), "l"(b));
}
__device__ __forceinline__ float2 unpack2(ull v) {
    float2 f;
    asm("mov.b64 {%0, %1}, %2;" : "=f"(f.x), "=f"(f.y) : "l"(v));
    return f;
}

// ---------------------------------------------------------------------------
__global__ void k_zero() {
    int i = blockIdx.x * 256 + threadIdx.x;
    if (i < BATCH * CH) { g_ksum[i] = 0.f; g_vsum[i] = 0.f; }
    if (i < BATCH * CH * CH) g_aggkv[i] = 0.f;
}

__global__ void k_twt(const float* __restrict__ W1, const float* __restrict__ W2) {
    int d = blockIdx.x * 256 + threadIdx.x;
    if (d >= 2 * CH * 9 * CH) return;
    const float* W = (d < CH * 9 * CH) ? W1 : W2;
    float* dst = (d < CH * 9 * CH) ? g_wt1 : g_wt2;
    int e = d % (CH * 9 * CH);
    int o = e & 63;
    int kk = (e >> 6) % 9;
    int i = e / (64 * 9);
    dst[e] = W[(o * 64 + i) * 9 + kk];    // W[o][i][ky][kx]
}

// ---------------------------------------------------------------------------
// 64x64 matvec, f32x2 accumulators (32 pairs = 64 outputs)
__device__ __forceinline__ void matvec64p(const float* __restrict__ ws,
                                          const float* __restrict__ bias,
                                          const float* __restrict__ xp,
                                          ull acc[32]) {
    const ulonglong2* b2 = (const ulonglong2*)bias;
#pragma unroll
    for (int j = 0; j < 16; j++) {
        ulonglong2 bb = b2[j];
        acc[2 * j] = bb.x; acc[2 * j + 1] = bb.y;
    }
#pragma unroll 4
    for (int c = 0; c < 64; c++) {
        ull xc = bcast2(__ldg(xp + ((size_t)c << 16)));
        const ulonglong2* w2 = (const ulonglong2*)(ws + c * 68);
#pragma unroll
        for (int j = 0; j < 16; j++) {
            ulonglong2 w = w2[j];
            fma2(acc[2 * j], w.x, xc);
            fma2(acc[2 * j + 1], w.y, xc);
        }
    }
}

#define SMEM_QKV ((3 * 64 * 68 + 2 * 64 * 256) * 4)

__global__ void __launch_bounds__(256, 1)
k_qkv(const float* __restrict__ x,
      const float* __restrict__ Wq, const float* __restrict__ bq,
      const float* __restrict__ Wk, const float* __restrict__ bk,
      const float* __restrict__ Wv, const float* __restrict__ bv) {
    extern __shared__ float sm[];
    float* wq_s = sm;
    float* wk_s = sm + 64 * 68;
    float* wv_s = sm + 2 * 64 * 68;
    float* k_s  = sm + 3 * 64 * 68;
    float* v_s  = k_s + 64 * 256;

    const int tid = threadIdx.x;
    const int b = blockIdx.x >> 8;
    const int n = ((blockIdx.x & 255) << 8) + tid;

    for (int idx = tid; idx < 4096; idx += 256) {
        int o = idx >> 6, c = idx & 63;
        wq_s[c * 68 + o] = Wq[idx];
        wk_s[c * 68 + o] = Wk[idx];
        wv_s[c * 68 + o] = Wv[idx];
    }
    __syncthreads();

    const float* xp = x + ((size_t)b << 22) + n;
    ull acc[32];
    float2 f;

    // ---- Q (normalized) ----
    matvec64p(wq_s, bq, xp, acc);
    float ss = 0.f;
#pragma unroll
    for (int j = 0; j < 32; j++) { f = unpack2(acc[j]); ss += f.x * f.x + f.y * f.y; }
    float inv = rsqrtf(ss);
#pragma unroll
    for (int j = 0; j < 32; j++) {
        f = unpack2(acc[j]);
        g_Qn[(((size_t)b * 64 + 2 * j) << 16) + n]     = f.x * inv;
        g_Qn[(((size_t)b * 64 + 2 * j + 1) << 16) + n] = f.y * inv;
    }

    // ---- K (normalized, to smem) ----
    matvec64p(wk_s, bk, xp, acc);
    ss = 0.f;
#pragma unroll
    for (int j = 0; j < 32; j++) { f = unpack2(acc[j]); ss += f.x * f.x + f.y * f.y; }
    inv = rsqrtf(ss);
#pragma unroll
    for (int j = 0; j < 32; j++) {
        f = unpack2(acc[j]);
        k_s[(2 * j) * 256 + tid]     = f.x * inv;
        k_s[(2 * j + 1) * 256 + tid] = f.y * inv;
    }

    // ---- V (to smem) ----
    matvec64p(wv_s, bv, xp, acc);
#pragma unroll
    for (int j = 0; j < 32; j++) {
        f = unpack2(acc[j]);
        v_s[(2 * j) * 256 + tid]     = f.x;
        v_s[(2 * j + 1) * 256 + tid] = f.y;
    }

    __syncthreads();

    // row sums -> ksum / vsum
    if (tid < 128) {
        int row = tid & 63;
        const float* src = (tid < 64) ? k_s : v_s;
        float s = 0.f;
        for (int i = 0; i < 256; i++) {
            int p = (i + tid) & 255;
            s += src[row * 256 + p];
        }
        float* dstp = (tid < 64) ? &g_ksum[b * 64 + row] : &g_vsum[b * 64 + row];
        atomicAdd(dstp, s);
    }

    // agg_kv[m][c] partial: 4x4 register blocking
    const int m0 = (tid >> 4) << 2;
    const int c0 = (tid & 15) << 2;
    float a[4][4];
#pragma unroll
    for (int i = 0; i < 4; i++)
#pragma unroll
        for (int j = 0; j < 4; j++) a[i][j] = 0.f;

    for (int it = 0; it < 256; it++) {
        int p = (it + tid) & 255;
        float kv0 = k_s[(m0 + 0) * 256 + p];
        float kv1 = k_s[(m0 + 1) * 256 + p];
        float kv2 = k_s[(m0 + 2) * 256 + p];
        float kv3 = k_s[(m0 + 3) * 256 + p];
        float vv0 = v_s[(c0 + 0) * 256 + p];
        float vv1 = v_s[(c0 + 1) * 256 + p];
        float vv2 = v_s[(c0 + 2) * 256 + p];
        float vv3 = v_s[(c0 + 3) * 256 + p];
        a[0][0] += kv0 * vv0; a[0][1] += kv0 * vv1; a[0][2] += kv0 * vv2; a[0][3] += kv0 * vv3;
        a[1][0] += kv1 * vv0; a[1][1] += kv1 * vv1; a[1][2] += kv1 * vv2; a[1][3] += kv1 * vv3;
        a[2][0] += kv2 * vv0; a[2][1] += kv2 * vv1; a[2][2] += kv2 * vv2; a[2][3] += kv2 * vv3;
        a[3][0] += kv3 * vv0; a[3][1] += kv3 * vv1; a[3][2] += kv3 * vv2; a[3][3] += kv3 * vv3;
    }
#pragma unroll
    for (int i = 0; i < 4; i++)
#pragma unroll
        for (int j = 0; j < 4; j++)
            atomicAdd(&g_aggkv[((size_t)b * 64 + m0 + i) * 64 + c0 + j], a[i][j]);
}

// ---------------------------------------------------------------------------
// k_fin v2: one block per batch, 256 threads, smem staging
__global__ void __launch_bounds__(256, 1)
k_fin(const float* __restrict__ Wr) {
    __shared__ float a_s[4096];   // aggkv [m][c]
    __shared__ float w_s[4096];   // Wr transposed [c][o]
    __shared__ float vs_s[64];

    int b = blockIdx.x;
    int tid = threadIdx.x;

    for (int idx = tid; idx < 4096; idx += 256) {
        a_s[idx] = g_aggkv[b * 4096 + idx];
        int o = idx & 63, c = idx >> 6;
        w_s[c * 64 + o] = Wr[o * 64 + c];   // consecutive-o writes: conflict-free
    }
    if (tid < 64) vs_s[tid] = g_vsum[b * 64 + tid];
    __syncthreads();

    int o = tid & 63, mg = tid >> 6;

    if (mg == 0) {
        float s = 0.f;
#pragma unroll 8
        for (int c = 0; c < 64; c++) s += w_s[c * 64 + o] * vs_s[c];
        g_wrvs[b * 64 + o] = s;
    }
#pragma unroll 1
    for (int m = mg * 16; m < mg * 16 + 16; m++) {
        float t = 0.f;
#pragma unroll 8
        for (int c = 0; c < 64; c++) t += w_s[c * 64 + o] * a_s[m * 64 + c];
        g_M2[(b * 64 + m) * 64 + o] = t;
    }
}

// ---------------------------------------------------------------------------
#define SMEM_ATTN ((64 * 64 + 64 * 256 + 64 + 64) * 4)

__global__ void __launch_bounds__(256, 1)
k_attn(const float* __restrict__ br) {
    extern __shared__ float sm[];
    float* m2_s = sm;                 // [m][o]
    float* q_s  = sm + 4096;          // [m][pixel]
    float* ks_s = q_s + 64 * 256;
    float* wv_s = ks_s + 64;

    const int tid = threadIdx.x;
    const int b = blockIdx.x >> 8;
    const int n = ((blockIdx.x & 255) << 8) + tid;

    for (int idx = tid; idx < 4096; idx += 256) m2_s[idx] = g_M2[b * 4096 + idx];
    if (tid < 64) {
        ks_s[tid] = g_ksum[b * 64 + tid] + 1e-6f;
        wv_s[tid] = g_wrvs[b * 64 + tid];
    }
#pragma unroll 1
    for (int m = 0; m < 64; m++)
        q_s[m * 256 + tid] = g_Qn[(((size_t)b * 64 + m) << 16) + n];
    __syncthreads();

    float dot = 0.f;
#pragma unroll 4
    for (int m = 0; m < 64; m++) dot += q_s[m * 256 + tid] * ks_s[m];
    float denom = 1.f / (65536.f + dot);

    ull acc[32];
    const ulonglong2* wv2 = (const ulonglong2*)wv_s;
#pragma unroll
    for (int j = 0; j < 16; j++) {
        ulonglong2 w = wv2[j];
        acc[2 * j] = w.x; acc[2 * j + 1] = w.y;
    }
#pragma unroll 4
    for (int m = 0; m < 64; m++) {
        ull qm = bcast2(q_s[m * 256 + tid]);
        const ulonglong2* w2 = (const ulonglong2*)(m2_s + m * 64);
#pragma unroll
        for (int j = 0; j < 16; j++) {
            ulonglong2 w = w2[j];
            fma2(acc[2 * j], w.x, qm);
            fma2(acc[2 * j + 1], w.y, qm);
        }
    }
#pragma unroll
    for (int j = 0; j < 32; j++) {
        float2 f = unpack2(acc[j]);
        g_attn[(((size_t)b * 64 + 2 * j) << 16) + n]     = f.x * denom + __ldg(&br[2 * j]);
        g_attn[(((size_t)b * 64 + 2 * j + 1) << 16) + n] = f.y * denom + __ldg(&br[2 * j + 1]);
    }
}

// ---------------------------------------------------------------------------
// 3x3 SAME conv, 64->64. Tile 32x16 pixels, 512 threads.
// Each thread: 2 pixels (rows ly, ly+8) x 32 output channels (o-split by tid>>8).
#define SMEM_CONV ((64 * 612 + 16 * 9 * 64) * 4)

__global__ void __launch_bounds__(512, 1)
k_conv(const float* __restrict__ src, const float* __restrict__ wt,
       const float* __restrict__ bias, float* __restrict__ dst,
       const float* __restrict__ xres, int fuse) {
    extern __shared__ float sm[];
    float* in_s = sm;                 // 64 * 612
    float* w_s  = sm + 64 * 612;      // 9216  [i16][tap][o]

    const int tid = threadIdx.x;
    const int bx = blockIdx.x & 7;
    const int by = (blockIdx.x >> 3) & 15;
    const int b  = blockIdx.x >> 7;
    const int tx0 = bx << 5, ty0 = by << 4;

    const float* sb = src + ((size_t)b << 22);

    // stage input tile (halo, zero-padded)
    for (int idx = tid; idx < 64 * 612; idx += 512) {
        int i = idx / 612;
        int r = idx % 612;
        int yy = r / 34, xx = r % 34;
        int gy = ty0 + yy - 1, gx = tx0 + xx - 1;
        float v = 0.f;
        if ((unsigned)gy < 256u && (unsigned)gx < 256u)
            v = sb[((size_t)i << 16) + (gy << 8) + gx];
        in_s[idx] = v;
    }

    const int lx = tid & 31;
    const int ly = (tid >> 5) & 7;     // pixel rows ly and ly+8
    const int os = tid >> 8;           // 0/1
    const int ob = os << 5;            // output-channel base

    ull acc[2][16];
    {
        const ulonglong2* b2 = (const ulonglong2*)(bias + ob);
#pragma unroll
        for (int j = 0; j < 8; j++) {
            ulonglong2 bb = b2[j];
            acc[0][2 * j] = bb.x; acc[0][2 * j + 1] = bb.y;
            acc[1][2 * j] = bb.x; acc[1][2 * j + 1] = bb.y;
        }
    }

    for (int ch = 0; ch < 4; ch++) {
        __syncthreads();   // covers input staging (ch=0) and w_s reuse
        for (int idx = tid; idx < 9216; idx += 512)
            w_s[idx] = wt[ch * 9216 + idx];
        __syncthreads();
#pragma unroll 1
        for (int ii = 0; ii < 16; ii++) {
            const float* ib0 = in_s + (ch * 16 + ii) * 612 + ly * 34 + lx;
            const float* ib1 = ib0 + 8 * 34;
            float x0[9], x1[9];
#pragma unroll
            for (int ky = 0; ky < 3; ky++)
#pragma unroll
                for (int kx = 0; kx < 3; kx++) {
                    x0[ky * 3 + kx] = ib0[ky * 34 + kx];
                    x1[ky * 3 + kx] = ib1[ky * 34 + kx];
                }
            const float* wb = w_s + ii * 576 + ob;
#pragma unroll
            for (int kk = 0; kk < 9; kk++) {
                ull p0 = bcast2(x0[kk]);
                ull p1 = bcast2(x1[kk]);
                const ulonglong2* w2 = (const ulonglong2*)(wb + kk * 64);
#pragma unroll
                for (int j = 0; j < 8; j++) {
                    ulonglong2 w = w2[j];
                    fma2(acc[0][2 * j],     w.x, p0);
                    fma2(acc[0][2 * j + 1], w.y, p0);
                    fma2(acc[1][2 * j],     w.x, p1);
                    fma2(acc[1][2 * j + 1], w.y, p1);
                }
            }
        }
    }

    const int gx = tx0 + lx;
#pragma unroll
    for (int p = 0; p < 2; p++) {
        const int gy = ty0 + ly + p * 8;
        const size_t base = ((size_t)b << 22) + (gy << 8) + gx;
        if (fuse) {
#pragma unroll
            for (int j = 0; j < 16; j++) {
                float2 f = unpack2(acc[p][j]);
                size_t i0 = base + ((size_t)(ob + 2 * j) << 16);
                size_t i1 = base + ((size_t)(ob + 2 * j + 1) << 16);
                float xv0 = xres[i0], xv1 = xres[i1];
                dst[i0] = f.x * xv0 + xv0;
                dst[i1] = f.y * xv1 + xv1;
            }
        } else {
#pragma unroll
            for (int j = 0; j < 16; j++) {
                float2 f = unpack2(acc[p][j]);
                dst[base + ((size_t)(ob + 2 * j) << 16)]     = f.x;
                dst[base + ((size_t)(ob + 2 * j + 1) << 16)] = f.y;
            }
        }
    }
}

// ---------------------------------------------------------------------------
extern "C" void kernel_launch(void* const* d_in, const int* in_sizes, int n_in,
                              void* d_out, int out_size) {
    const float* x  = (const float*)d_in[0];
    const float* Wq = (const float*)d_in[1];
    const float* bq = (const float*)d_in[2];
    const float* Wk = (const float*)d_in[3];
    const float* bk = (const float*)d_in[4];
    const float* Wv = (const float*)d_in[5];
    const float* bv = (const float*)d_in[6];
    const float* Wr = (const float*)d_in[7];
    const float* br = (const float*)d_in[8];
    const float* W1 = (const float*)d_in[9];
    const float* b1 = (const float*)d_in[10];
    const float* W2 = (const float*)d_in[11];
    const float* b2 = (const float*)d_in[12];
    float* out = (float*)d_out;

    cudaFuncSetAttribute(k_qkv,  cudaFuncAttributeMaxDynamicSharedMemorySize, SMEM_QKV);
    cudaFuncSetAttribute(k_attn, cudaFuncAttributeMaxDynamicSharedMemorySize, SMEM_ATTN);
    cudaFuncSetAttribute(k_conv, cudaFuncAttributeMaxDynamicSharedMemorySize, SMEM_CONV);

    void *p_attn, *p_t1, *p_wt1, *p_wt2;
    cudaGetSymbolAddress(&p_attn, g_attn);
    cudaGetSymbolAddress(&p_t1, g_t1);
    cudaGetSymbolAddress(&p_wt1, g_wt1);
    cudaGetSymbolAddress(&p_wt2, g_wt2);

    k_zero<<<128, 256>>>();
    k_twt<<<288, 256>>>(W1, W2);
    k_qkv<<<2048, 256, SMEM_QKV>>>(x, Wq, bq, Wk, bk, Wv, bv);
    k_fin<<<8, 256>>>(Wr);
    k_attn<<<2048, 256, SMEM_ATTN>>>(br);
    k_conv<<<1024, 512, SMEM_CONV>>>((const float*)p_attn, (const float*)p_wt1,
                                     b1, (float*)p_t1, nullptr, 0);
    k_conv<<<1024, 512, SMEM_CONV>>>((const float*)p_t1, (const float*)p_wt2,
                                     b2, out, x, 1);
}

// round 4
// speedup vs baseline: 1.5896x; 1.1544x over previous
#include <cuda_runtime.h>
#include <cstdint>

// ---------------------------------------------------------------------------
// HydraAttention_v2 — qkv/attn in fp32 FFMA2, 3x3 convs via mma.sync tf32
// (compute_103-safe: no tcgen05 / clusters — ptxas target lacks the 'a' suffix)
// B=8, C=64, H=W=256, N=65536
// ---------------------------------------------------------------------------

#define BATCH 8
#define CH    64
#define NPIX  65536

typedef unsigned long long ull;

__device__ float g_Qn[BATCH * CH * NPIX];
__device__ float g_attn[BATCH * CH * NPIX];
__device__ float g_t1[BATCH * CH * NPIX];
__device__ float g_ksum[BATCH * CH];
__device__ float g_vsum[BATCH * CH];
__device__ float g_aggkv[BATCH * CH * CH];
__device__ float g_M2[BATCH * CH * CH];
__device__ float g_wrvs[BATCH * CH];
// conv weights, tf32-rounded: [conv][chunk 72][n 64][tig 4][pair 2]
__device__ uint32_t g_convB[2 * 72 * 64 * 8];

// ---- packed fp32 helpers ----------------------------------------------------
__device__ __forceinline__ ull bcast2(float v) {
    ull r; asm("mov.b64 %0, {%1, %1};" : "=l"(r) : "f"(v)); return r;
}
__device__ __forceinline__ void fma2(ull& d, ull a, ull b) {
    asm("fma.rn.f32x2 %0, %1, %2, %0;" : "+l"(d) : "l"(a), "l"(b));
}
__device__ __forceinline__ float2 unpack2(ull v) {
    float2 f; asm("mov.b64 {%0, %1}, %2;" : "=f"(f.x), "=f"(f.y) : "l"(v)); return f;
}

// ---- mma.sync tf32 helper ---------------------------------------------------
__device__ __forceinline__ void mma_tf32(float c[4], uint32_t a0, uint32_t a1,
                                         uint32_t a2, uint32_t a3,
                                         uint32_t b0, uint32_t b1) {
    asm volatile(
        "mma.sync.aligned.m16n8k8.row.col.f32.tf32.tf32.f32 "
        "{%0,%1,%2,%3}, {%4,%5,%6,%7}, {%8,%9}, {%0,%1,%2,%3};"
        : "+f"(c[0]), "+f"(c[1]), "+f"(c[2]), "+f"(c[3])
        : "r"(a0), "r"(a1), "r"(a2), "r"(a3), "r"(b0), "r"(b1));
}
__device__ __forceinline__ uint32_t f2tf32(float v) {
    uint32_t r;
    asm("cvt.rna.tf32.f32 %0, %1;" : "=r"(r) : "f"(v));
    return r;
}

// ---------------------------------------------------------------------------
__global__ void k_zero() {
    int i = blockIdx.x * 256 + threadIdx.x;
    if (i < BATCH * CH) { g_ksum[i] = 0.f; g_vsum[i] = 0.f; }
    if (i < BATCH * CH * CH) g_aggkv[i] = 0.f;
}

// prep conv B fragments. chunk c = tap*8 + kc; pair = (ch 8kc+tig, 8kc+tig+4)
__global__ void k_prepB(const float* __restrict__ W1, const float* __restrict__ W2) {
    int f = blockIdx.x * 256 + threadIdx.x;
    if (f >= 73728) return;
    int j    = f & 1;
    int tig  = (f >> 1) & 3;
    int n    = (f >> 3) & 63;
    int rest = f >> 9;              // 0..143
    int c    = rest % 72;
    int conv = rest / 72;
    int kc = c & 7, tap = c >> 3;
    int ch = 8 * kc + tig + 4 * j;
    const float* W = conv ? W2 : W1;
    g_convB[f] = f2tf32(W[n * 576 + ch * 9 + tap]);
}

// ---------------------------------------------------------------------------
__device__ __forceinline__ void matvec64p(const float* __restrict__ ws,
                                          const float* __restrict__ bias,
                                          const float* __restrict__ xp,
                                          ull acc[32]) {
    const ulonglong2* b2 = (const ulonglong2*)bias;
#pragma unroll
    for (int j = 0; j < 16; j++) {
        ulonglong2 bb = b2[j];
        acc[2 * j] = bb.x; acc[2 * j + 1] = bb.y;
    }
#pragma unroll 4
    for (int c = 0; c < 64; c++) {
        ull xc = bcast2(__ldg(xp + ((size_t)c << 16)));
        const ulonglong2* w2 = (const ulonglong2*)(ws + c * 68);
#pragma unroll
        for (int j = 0; j < 16; j++) {
            ulonglong2 w = w2[j];
            fma2(acc[2 * j], w.x, xc);
            fma2(acc[2 * j + 1], w.y, xc);
        }
    }
}

#define SMEM_QKV ((3 * 64 * 68 + 2 * 64 * 256) * 4)

__global__ void __launch_bounds__(256, 1)
k_qkv(const float* __restrict__ x,
      const float* __restrict__ Wq, const float* __restrict__ bq,
      const float* __restrict__ Wk, const float* __restrict__ bk,
      const float* __restrict__ Wv, const float* __restrict__ bv) {
    extern __shared__ float sm[];
    float* wq_s = sm;
    float* wk_s = sm + 64 * 68;
    float* wv_s = sm + 2 * 64 * 68;
    float* k_s  = sm + 3 * 64 * 68;
    float* v_s  = k_s + 64 * 256;

    const int tid = threadIdx.x;
    const int b = blockIdx.x >> 8;
    const int n = ((blockIdx.x & 255) << 8) + tid;

    for (int idx = tid; idx < 4096; idx += 256) {
        int o = idx >> 6, c = idx & 63;
        wq_s[c * 68 + o] = Wq[idx];
        wk_s[c * 68 + o] = Wk[idx];
        wv_s[c * 68 + o] = Wv[idx];
    }
    __syncthreads();

    const float* xp = x + ((size_t)b << 22) + n;
    ull acc[32];
    float2 f;

    matvec64p(wq_s, bq, xp, acc);
    float ss = 0.f;
#pragma unroll
    for (int j = 0; j < 32; j++) { f = unpack2(acc[j]); ss += f.x * f.x + f.y * f.y; }
    float inv = rsqrtf(ss);
#pragma unroll
    for (int j = 0; j < 32; j++) {
        f = unpack2(acc[j]);
        g_Qn[(((size_t)b * 64 + 2 * j) << 16) + n]     = f.x * inv;
        g_Qn[(((size_t)b * 64 + 2 * j + 1) << 16) + n] = f.y * inv;
    }

    matvec64p(wk_s, bk, xp, acc);
    ss = 0.f;
#pragma unroll
    for (int j = 0; j < 32; j++) { f = unpack2(acc[j]); ss += f.x * f.x + f.y * f.y; }
    inv = rsqrtf(ss);
#pragma unroll
    for (int j = 0; j < 32; j++) {
        f = unpack2(acc[j]);
        k_s[(2 * j) * 256 + tid]     = f.x * inv;
        k_s[(2 * j + 1) * 256 + tid] = f.y * inv;
    }

    matvec64p(wv_s, bv, xp, acc);
#pragma unroll
    for (int j = 0; j < 32; j++) {
        f = unpack2(acc[j]);
        v_s[(2 * j) * 256 + tid]     = f.x;
        v_s[(2 * j + 1) * 256 + tid] = f.y;
    }
    __syncthreads();

    if (tid < 128) {
        int row = tid & 63;
        const float* src = (tid < 64) ? k_s : v_s;
        float s = 0.f;
        for (int i = 0; i < 256; i++) {
            int p = (i + tid) & 255;
            s += src[row * 256 + p];
        }
        float* dstp = (tid < 64) ? &g_ksum[b * 64 + row] : &g_vsum[b * 64 + row];
        atomicAdd(dstp, s);
    }

    const int m0 = (tid >> 4) << 2;
    const int c0 = (tid & 15) << 2;
    float a[4][4];
#pragma unroll
    for (int i = 0; i < 4; i++)
#pragma unroll
        for (int j = 0; j < 4; j++) a[i][j] = 0.f;

    for (int it = 0; it < 256; it++) {
        int p = (it + tid) & 255;
        float kv0 = k_s[(m0 + 0) * 256 + p];
        float kv1 = k_s[(m0 + 1) * 256 + p];
        float kv2 = k_s[(m0 + 2) * 256 + p];
        float kv3 = k_s[(m0 + 3) * 256 + p];
        float vv0 = v_s[(c0 + 0) * 256 + p];
        float vv1 = v_s[(c0 + 1) * 256 + p];
        float vv2 = v_s[(c0 + 2) * 256 + p];
        float vv3 = v_s[(c0 + 3) * 256 + p];
        a[0][0] += kv0 * vv0; a[0][1] += kv0 * vv1; a[0][2] += kv0 * vv2; a[0][3] += kv0 * vv3;
        a[1][0] += kv1 * vv0; a[1][1] += kv1 * vv1; a[1][2] += kv1 * vv2; a[1][3] += kv1 * vv3;
        a[2][0] += kv2 * vv0; a[2][1] += kv2 * vv1; a[2][2] += kv2 * vv2; a[2][3] += kv2 * vv3;
        a[3][0] += kv3 * vv0; a[3][1] += kv3 * vv1; a[3][2] += kv3 * vv2; a[3][3] += kv3 * vv3;
    }
#pragma unroll
    for (int i = 0; i < 4; i++)
#pragma unroll
        for (int j = 0; j < 4; j++)
            atomicAdd(&g_aggkv[((size_t)b * 64 + m0 + i) * 64 + c0 + j], a[i][j]);
}

// ---------------------------------------------------------------------------
__global__ void __launch_bounds__(256, 1)
k_fin(const float* __restrict__ Wr) {
    __shared__ float a_s[4096];
    __shared__ float w_s[4096];
    __shared__ float vs_s[64];

    int b = blockIdx.x;
    int tid = threadIdx.x;

    for (int idx = tid; idx < 4096; idx += 256) {
        a_s[idx] = g_aggkv[b * 4096 + idx];
        int o = idx & 63, c = idx >> 6;
        w_s[c * 64 + o] = Wr[o * 64 + c];
    }
    if (tid < 64) vs_s[tid] = g_vsum[b * 64 + tid];
    __syncthreads();

    int o = tid & 63, mg = tid >> 6;
    if (mg == 0) {
        float s = 0.f;
#pragma unroll 8
        for (int c = 0; c < 64; c++) s += w_s[c * 64 + o] * vs_s[c];
        g_wrvs[b * 64 + o] = s;
    }
#pragma unroll 1
    for (int m = mg * 16; m < mg * 16 + 16; m++) {
        float t = 0.f;
#pragma unroll 8
        for (int c = 0; c < 64; c++) t += w_s[c * 64 + o] * a_s[m * 64 + c];
        g_M2[(b * 64 + m) * 64 + o] = t;
    }
}

// ---------------------------------------------------------------------------
#define SMEM_ATTN ((64 * 64 + 64 * 256 + 64 + 64) * 4)

__global__ void __launch_bounds__(256, 1)
k_attn(const float* __restrict__ br) {
    extern __shared__ float sm[];
    float* m2_s = sm;
    float* q_s  = sm + 4096;
    float* ks_s = q_s + 64 * 256;
    float* wv_s = ks_s + 64;

    const int tid = threadIdx.x;
    const int b = blockIdx.x >> 8;
    const int n = ((blockIdx.x & 255) << 8) + tid;

    for (int idx = tid; idx < 4096; idx += 256) m2_s[idx] = g_M2[b * 4096 + idx];
    if (tid < 64) {
        ks_s[tid] = g_ksum[b * 64 + tid] + 1e-6f;
        wv_s[tid] = g_wrvs[b * 64 + tid];
    }
#pragma unroll 1
    for (int m = 0; m < 64; m++)
        q_s[m * 256 + tid] = g_Qn[(((size_t)b * 64 + m) << 16) + n];
    __syncthreads();

    float dot = 0.f;
#pragma unroll 4
    for (int m = 0; m < 64; m++) dot += q_s[m * 256 + tid] * ks_s[m];
    float denom = 1.f / (65536.f + dot);

    ull acc[32];
    const ulonglong2* wv2 = (const ulonglong2*)wv_s;
#pragma unroll
    for (int j = 0; j < 16; j++) {
        ulonglong2 w = wv2[j];
        acc[2 * j] = w.x; acc[2 * j + 1] = w.y;
    }
#pragma unroll 4
    for (int m = 0; m < 64; m++) {
        ull qm = bcast2(q_s[m * 256 + tid]);
        const ulonglong2* w2 = (const ulonglong2*)(m2_s + m * 64);
#pragma unroll
        for (int j = 0; j < 16; j++) {
            ulonglong2 w = w2[j];
            fma2(acc[2 * j], w.x, qm);
            fma2(acc[2 * j + 1], w.y, qm);
        }
    }
#pragma unroll
    for (int j = 0; j < 32; j++) {
        float2 f = unpack2(acc[j]);
        g_attn[(((size_t)b * 64 + 2 * j) << 16) + n]     = f.x * denom + __ldg(&br[2 * j]);
        g_attn[(((size_t)b * 64 + 2 * j + 1) << 16) + n] = f.y * denom + __ldg(&br[2 * j + 1]);
    }
}

// ---------------------------------------------------------------------------
// conv3x3 via mma.sync tf32.
// Block: 8-row band x 128-px x-half x 32-out n-half. 256 threads (8 warps),
// warp w covers pixels [16w, 16w+16) of the x-half, all 32 outs.
// smem layout (bytes):
//   [0]      bias 64 f                      (256)
//   [256]    B half: 72 chunks * 1KB        (73728)   [chunk][n 32][tig 4][2]
//   [74240]  A ring: 4 slots * 37440        (149760)  [hx 130][pad-72w: kc 8][tig 4][2]
// total 224000
#define CB_OFF   256
#define CA_OFF   74240
#define CA_SLOT  37440          // 130 * 72 words * 4
#define CV_SMEM  224000

__device__ __forceinline__ void cv_stage_row(char* smem, int slot,
                                             const float* __restrict__ src,
                                             int b, int gy, int x0, int tid) {
    uint32_t* dstw = (uint32_t*)(smem + CA_OFF + slot * CA_SLOT);
    if ((unsigned)gy < 256u) {
        const float* sp = src + ((size_t)b << 22) + ((size_t)gy << 8);
        for (int i = tid; i < 8320; i += 256) {
            int ch = i / 130;
            int hx = i - ch * 130;
            int gx = x0 - 1 + hx;
            float v = 0.f;
            if ((unsigned)gx < 256u) v = __ldg(sp + ((size_t)ch << 16) + gx);
            // word = hx*72 + kc*8 + tig*2 + j ; ch = 8kc + tig + 4j
            int w = hx * 72 + (ch >> 3) * 8 + (ch & 3) * 2 + ((ch >> 2) & 1);
            dstw[w] = f2tf32(v);
        }
    } else {
        for (int i = tid; i < 8320; i += 256) {
            int ch = i / 130;
            int hx = i - ch * 130;
            int w = hx * 72 + (ch >> 3) * 8 + (ch & 3) * 2 + ((ch >> 2) & 1);
            dstw[w] = 0u;
        }
    }
}

__global__ void __launch_bounds__(256, 1)
k_conv_mma(const float* __restrict__ src, const float* __restrict__ bias,
           float* __restrict__ dst, const float* __restrict__ xres,
           int fuse, int convIdx) {
    extern __shared__ char smc[];
    const int tid = threadIdx.x;
    const int wid = tid >> 5;
    const int lane = tid & 31;
    const int g   = lane >> 2;    // groupID
    const int tig = lane & 3;     // threadID in group

    const int nh   = blockIdx.x & 1;
    const int xh   = (blockIdx.x >> 1) & 1;
    const int band = (blockIdx.x >> 2) & 31;
    const int b    = blockIdx.x >> 7;
    const int y0   = band << 3;
    const int x0   = xh << 7;

    // stage bias + B half
    if (tid < 64) ((float*)smc)[tid] = bias[tid];
    {
        const uint4* bsrc = (const uint4*)(g_convB + convIdx * 36864 + nh * 256);
        uint4* bdst = (uint4*)(smc + CB_OFF);
        for (int q = tid; q < 4608; q += 256) {
            int c = q >> 6;               // chunk
            int r = q & 63;               // 16B unit within 256B quarter? (w&255)/4
            bdst[q] = bsrc[c * 128 + r];  // src row stride 512 words = 128 uint4
        }
    }

    // prologue: rows y0-1, y0, y0+1 ; slot(gy) = (gy+1)&3
    cv_stage_row(smc, (y0) & 3,     src, b, y0 - 1, x0, tid);
    cv_stage_row(smc, (y0 + 1) & 3, src, b, y0,     x0, tid);
    cv_stage_row(smc, (y0 + 2) & 3, src, b, y0 + 1, x0, tid);
    __syncthreads();

    const int px0 = wid << 4;     // 16 px per warp
    const char* bBase = smc + CB_OFF + (g << 5) + (tig << 3);

    for (int t = 0; t < 8; t++) {
        const int y = y0 + t;

        float acc[4][4];
#pragma unroll
        for (int nt = 0; nt < 4; nt++)
#pragma unroll
            for (int r = 0; r < 4; r++) acc[nt][r] = 0.f;

#pragma unroll 1
        for (int ky = 0; ky < 3; ky++) {
            const char* aSlot = smc + CA_OFF + ((y + ky) & 3) * CA_SLOT;
#pragma unroll 1
            for (int kx = 0; kx < 3; kx++) {
                // hx for row m of the fragment: px0 + g(+8) + kx
                const char* aCol = aSlot + (px0 + g + kx) * 288 + (tig << 3);
                const char* bCk  = bBase + (ky * 3 + kx) * 8192;
#pragma unroll
                for (int kc = 0; kc < 8; kc++) {
                    uint2 A0 = *(const uint2*)(aCol + kc * 32);            // a0,a2
                    uint2 A1 = *(const uint2*)(aCol + 8 * 288 + kc * 32);  // a1,a3
                    const char* bc = bCk + kc * 1024;
                    uint2 B0 = *(const uint2*)(bc);
                    uint2 B1 = *(const uint2*)(bc + 256);
                    uint2 B2 = *(const uint2*)(bc + 512);
                    uint2 B3 = *(const uint2*)(bc + 768);
                    mma_tf32(acc[0], A0.x, A1.x, A0.y, A1.y, B0.x, B0.y);
                    mma_tf32(acc[1], A0.x, A1.x, A0.y, A1.y, B1.x, B1.y);
                    mma_tf32(acc[2], A0.x, A1.x, A0.y, A1.y, B2.x, B2.y);
                    mma_tf32(acc[3], A0.x, A1.x, A0.y, A1.y, B3.x, B3.y);
                }
            }
        }

        // epilogue: c0 -> (px0+g, 2tig), c1 -> +1 col, c2/c3 -> px0+g+8
        {
            const float* bs = (const float*)smc;
            const int pxA = x0 + px0 + g;
            const int pxB = pxA + 8;
            const size_t rowOff = ((size_t)b << 22) + ((size_t)y << 8);
#pragma unroll
            for (int nt = 0; nt < 4; nt++) {
                int o0 = nh * 32 + nt * 8 + tig * 2;
#pragma unroll
                for (int e = 0; e < 2; e++) {
                    int o = o0 + e;
                    float bb = bs[o];
                    size_t iA = rowOff + ((size_t)o << 16) + pxA;
                    size_t iB = rowOff + ((size_t)o << 16) + pxB;
                    float vA = acc[nt][e] + bb;
                    float vB = acc[nt][2 + e] + bb;
                    if (fuse) {
                        float xA = xres[iA], xB = xres[iB];
                        dst[iA] = vA * xA + xA;
                        dst[iB] = vB * xB + xB;
                    } else {
                        dst[iA] = vA;
                        dst[iB] = vB;
                    }
                }
            }
        }

        // stage row y+2 into free slot (y+3)&3
        if (t < 7) cv_stage_row(smc, (y + 3) & 3, src, b, y + 2, x0, tid);
        __syncthreads();
    }
}

// ---------------------------------------------------------------------------
extern "C" void kernel_launch(void* const* d_in, const int* in_sizes, int n_in,
                              void* d_out, int out_size) {
    const float* x  = (const float*)d_in[0];
    const float* Wq = (const float*)d_in[1];
    const float* bq = (const float*)d_in[2];
    const float* Wk = (const float*)d_in[3];
    const float* bk = (const float*)d_in[4];
    const float* Wv = (const float*)d_in[5];
    const float* bv = (const float*)d_in[6];
    const float* Wr = (const float*)d_in[7];
    const float* br = (const float*)d_in[8];
    const float* W1 = (const float*)d_in[9];
    const float* b1 = (const float*)d_in[10];
    const float* W2 = (const float*)d_in[11];
    const float* b2 = (const float*)d_in[12];
    float* out = (float*)d_out;

    cudaFuncSetAttribute(k_qkv,      cudaFuncAttributeMaxDynamicSharedMemorySize, SMEM_QKV);
    cudaFuncSetAttribute(k_attn,     cudaFuncAttributeMaxDynamicSharedMemorySize, SMEM_ATTN);
    cudaFuncSetAttribute(k_conv_mma, cudaFuncAttributeMaxDynamicSharedMemorySize, CV_SMEM);

    void *p_attn, *p_t1;
    cudaGetSymbolAddress(&p_attn, g_attn);
    cudaGetSymbolAddress(&p_t1, g_t1);

    k_zero<<<128, 256>>>();
    k_prepB<<<288, 256>>>(W1, W2);
    k_qkv<<<2048, 256, SMEM_QKV>>>(x, Wq, bq, Wk, bk, Wv, bv);
    k_fin<<<8, 256>>>(Wr);
    k_attn<<<2048, 256, SMEM_ATTN>>>(br);
    k_conv_mma<<<1024, 256, CV_SMEM>>>((const float*)p_attn, b1, (float*)p_t1,
                                       nullptr, 0, 0);
    k_conv_mma<<<1024, 256, CV_SMEM>>>((const float*)p_t1, b2, out, x, 1, 1);
}

// round 5
// speedup vs baseline: 1.9476x; 1.2252x over previous
#include <cuda_runtime.h>
#include <cuda_fp16.h>
#include <cstdint>

// ---------------------------------------------------------------------------
// HydraAttention_v2 — qkv/attn in fp32 FFMA2, 3x3 convs via mma.sync fp16 k16
// B=8, C=64, H=W=256, N=65536
// ---------------------------------------------------------------------------

#define BATCH 8
#define CH    64
#define NPIX  65536

typedef unsigned long long ull;

__device__ float g_Qn[BATCH * CH * NPIX];
__device__ float g_attn[BATCH * CH * NPIX];
__device__ float g_t1[BATCH * CH * NPIX];
__device__ float g_ksum[BATCH * CH];
__device__ float g_vsum[BATCH * CH];
__device__ float g_aggkv[BATCH * CH * CH];
__device__ float g_M2[BATCH * CH * CH];
__device__ float g_wrvs[BATCH * CH];
// conv weights fp16x2: [conv][chunk 36][n 64][tig 4][s 2] words
__device__ uint32_t g_convB[2 * 36 * 64 * 8];

// ---- packed fp32 helpers ----------------------------------------------------
__device__ __forceinline__ ull bcast2(float v) {
    ull r; asm("mov.b64 %0, {%1, %1};" : "=l"(r) : "f"(v)); return r;
}
__device__ __forceinline__ void fma2(ull& d, ull a, ull b) {
    asm("fma.rn.f32x2 %0, %1, %2, %0;" : "+l"(d) : "l"(a), "l"(b));
}
__device__ __forceinline__ float2 unpack2(ull v) {
    float2 f; asm("mov.b64 {%0, %1}, %2;" : "=f"(f.x), "=f"(f.y) : "l"(v)); return f;
}

// ---- mma.sync fp16 helper -----------------------------------------------------
__device__ __forceinline__ void mma_fp16(float c[4], uint32_t a0, uint32_t a1,
                                         uint32_t a2, uint32_t a3,
                                         uint32_t b0, uint32_t b1) {
    asm volatile(
        "mma.sync.aligned.m16n8k16.row.col.f32.f16.f16.f32 "
        "{%0,%1,%2,%3}, {%4,%5,%6,%7}, {%8,%9}, {%0,%1,%2,%3};"
        : "+f"(c[0]), "+f"(c[1]), "+f"(c[2]), "+f"(c[3])
        : "r"(a0), "r"(a1), "r"(a2), "r"(a3), "r"(b0), "r"(b1));
}

// ---------------------------------------------------------------------------
__global__ void k_zero() {
    int i = blockIdx.x * 256 + threadIdx.x;
    if (i < BATCH * CH) { g_ksum[i] = 0.f; g_vsum[i] = 0.f; }
    if (i < BATCH * CH * CH) g_aggkv[i] = 0.f;
}

// prep conv B fragments (fp16x2 words).
// chunk = tap*4 + kc ; word packs ch = kc*16 + 2*tig + 8*s (+0,+1)
__global__ void k_prepB(const float* __restrict__ W1, const float* __restrict__ W2) {
    int f = blockIdx.x * 256 + threadIdx.x;
    if (f >= 36864) return;
    int conv = f / 18432;
    int r    = f % 18432;
    int chunk = r >> 9;
    int w     = r & 511;
    int n   = w >> 3;
    int ww  = w & 7;
    int tig = ww >> 1;
    int s   = ww & 1;
    int tap = chunk >> 2, kc = chunk & 3;
    int ch = kc * 16 + 2 * tig + 8 * s;
    const float* W = conv ? W2 : W1;
    float f0 = W[n * 576 + ch * 9 + tap];
    float f1 = W[n * 576 + (ch + 1) * 9 + tap];
    __half2 h = __float22half2_rn(make_float2(f0, f1));
    g_convB[f] = *(uint32_t*)&h;
}

// ---------------------------------------------------------------------------
__device__ __forceinline__ void matvec64p(const float* __restrict__ ws,
                                          const float* __restrict__ bias,
                                          const float* __restrict__ xp,
                                          ull acc[32]) {
    const ulonglong2* b2 = (const ulonglong2*)bias;
#pragma unroll
    for (int j = 0; j < 16; j++) {
        ulonglong2 bb = b2[j];
        acc[2 * j] = bb.x; acc[2 * j + 1] = bb.y;
    }
#pragma unroll 4
    for (int c = 0; c < 64; c++) {
        ull xc = bcast2(__ldg(xp + ((size_t)c << 16)));
        const ulonglong2* w2 = (const ulonglong2*)(ws + c * 68);
#pragma unroll
        for (int j = 0; j < 16; j++) {
            ulonglong2 w = w2[j];
            fma2(acc[2 * j], w.x, xc);
            fma2(acc[2 * j + 1], w.y, xc);
        }
    }
}

#define SMEM_QKV ((3 * 64 * 68 + 2 * 64 * 256) * 4)

__global__ void __launch_bounds__(256, 1)
k_qkv(const float* __restrict__ x,
      const float* __restrict__ Wq, const float* __restrict__ bq,
      const float* __restrict__ Wk, const float* __restrict__ bk,
      const float* __restrict__ Wv, const float* __restrict__ bv) {
    extern __shared__ float sm[];
    float* wq_s = sm;
    float* wk_s = sm + 64 * 68;
    float* wv_s = sm + 2 * 64 * 68;
    float* k_s  = sm + 3 * 64 * 68;
    float* v_s  = k_s + 64 * 256;

    const int tid = threadIdx.x;
    const int b = blockIdx.x >> 8;
    const int n = ((blockIdx.x & 255) << 8) + tid;

    for (int idx = tid; idx < 4096; idx += 256) {
        int o = idx >> 6, c = idx & 63;
        wq_s[c * 68 + o] = Wq[idx];
        wk_s[c * 68 + o] = Wk[idx];
        wv_s[c * 68 + o] = Wv[idx];
    }
    __syncthreads();

    const float* xp = x + ((size_t)b << 22) + n;
    ull acc[32];
    float2 f;

    matvec64p(wq_s, bq, xp, acc);
    float ss = 0.f;
#pragma unroll
    for (int j = 0; j < 32; j++) { f = unpack2(acc[j]); ss += f.x * f.x + f.y * f.y; }
    float inv = rsqrtf(ss);
#pragma unroll
    for (int j = 0; j < 32; j++) {
        f = unpack2(acc[j]);
        g_Qn[(((size_t)b * 64 + 2 * j) << 16) + n]     = f.x * inv;
        g_Qn[(((size_t)b * 64 + 2 * j + 1) << 16) + n] = f.y * inv;
    }

    matvec64p(wk_s, bk, xp, acc);
    ss = 0.f;
#pragma unroll
    for (int j = 0; j < 32; j++) { f = unpack2(acc[j]); ss += f.x * f.x + f.y * f.y; }
    inv = rsqrtf(ss);
#pragma unroll
    for (int j = 0; j < 32; j++) {
        f = unpack2(acc[j]);
        k_s[(2 * j) * 256 + tid]     = f.x * inv;
        k_s[(2 * j + 1) * 256 + tid] = f.y * inv;
    }

    matvec64p(wv_s, bv, xp, acc);
#pragma unroll
    for (int j = 0; j < 32; j++) {
        f = unpack2(acc[j]);
        v_s[(2 * j) * 256 + tid]     = f.x;
        v_s[(2 * j + 1) * 256 + tid] = f.y;
    }
    __syncthreads();

    if (tid < 128) {
        int row = tid & 63;
        const float* src = (tid < 64) ? k_s : v_s;
        float s = 0.f;
        for (int i = 0; i < 256; i++) {
            int p = (i + tid) & 255;
            s += src[row * 256 + p];
        }
        float* dstp = (tid < 64) ? &g_ksum[b * 64 + row] : &g_vsum[b * 64 + row];
        atomicAdd(dstp, s);
    }

    const int m0 = (tid >> 4) << 2;
    const int c0 = (tid & 15) << 2;
    float a[4][4];
#pragma unroll
    for (int i = 0; i < 4; i++)
#pragma unroll
        for (int j = 0; j < 4; j++) a[i][j] = 0.f;

    for (int it = 0; it < 256; it++) {
        int p = (it + tid) & 255;
        float kv0 = k_s[(m0 + 0) * 256 + p];
        float kv1 = k_s[(m0 + 1) * 256 + p];
        float kv2 = k_s[(m0 + 2) * 256 + p];
        float kv3 = k_s[(m0 + 3) * 256 + p];
        float vv0 = v_s[(c0 + 0) * 256 + p];
        float vv1 = v_s[(c0 + 1) * 256 + p];
        float vv2 = v_s[(c0 + 2) * 256 + p];
        float vv3 = v_s[(c0 + 3) * 256 + p];
        a[0][0] += kv0 * vv0; a[0][1] += kv0 * vv1; a[0][2] += kv0 * vv2; a[0][3] += kv0 * vv3;
        a[1][0] += kv1 * vv0; a[1][1] += kv1 * vv1; a[1][2] += kv1 * vv2; a[1][3] += kv1 * vv3;
        a[2][0] += kv2 * vv0; a[2][1] += kv2 * vv1; a[2][2] += kv2 * vv2; a[2][3] += kv2 * vv3;
        a[3][0] += kv3 * vv0; a[3][1] += kv3 * vv1; a[3][2] += kv3 * vv2; a[3][3] += kv3 * vv3;
    }
#pragma unroll
    for (int i = 0; i < 4; i++)
#pragma unroll
        for (int j = 0; j < 4; j++)
            atomicAdd(&g_aggkv[((size_t)b * 64 + m0 + i) * 64 + c0 + j], a[i][j]);
}

// ---------------------------------------------------------------------------
__global__ void __launch_bounds__(256, 1)
k_fin(const float* __restrict__ Wr) {
    __shared__ float a_s[4096];
    __shared__ float w_s[4096];
    __shared__ float vs_s[64];

    int b = blockIdx.x;
    int tid = threadIdx.x;

    for (int idx = tid; idx < 4096; idx += 256) {
        a_s[idx] = g_aggkv[b * 4096 + idx];
        int o = idx & 63, c = idx >> 6;
        w_s[c * 64 + o] = Wr[o * 64 + c];
    }
    if (tid < 64) vs_s[tid] = g_vsum[b * 64 + tid];
    __syncthreads();

    int o = tid & 63, mg = tid >> 6;
    if (mg == 0) {
        float s = 0.f;
#pragma unroll 8
        for (int c = 0; c < 64; c++) s += w_s[c * 64 + o] * vs_s[c];
        g_wrvs[b * 64 + o] = s;
    }
#pragma unroll 1
    for (int m = mg * 16; m < mg * 16 + 16; m++) {
        float t = 0.f;
#pragma unroll 8
        for (int c = 0; c < 64; c++) t += w_s[c * 64 + o] * a_s[m * 64 + c];
        g_M2[(b * 64 + m) * 64 + o] = t;
    }
}

// ---------------------------------------------------------------------------
#define SMEM_ATTN ((64 * 64 + 64 * 256 + 64 + 64) * 4)

__global__ void __launch_bounds__(256, 1)
k_attn(const float* __restrict__ br) {
    extern __shared__ float sm[];
    float* m2_s = sm;
    float* q_s  = sm + 4096;
    float* ks_s = q_s + 64 * 256;
    float* wv_s = ks_s + 64;

    const int tid = threadIdx.x;
    const int b = blockIdx.x >> 8;
    const int n = ((blockIdx.x & 255) << 8) + tid;

    for (int idx = tid; idx < 4096; idx += 256) m2_s[idx] = g_M2[b * 4096 + idx];
    if (tid < 64) {
        ks_s[tid] = g_ksum[b * 64 + tid] + 1e-6f;
        wv_s[tid] = g_wrvs[b * 64 + tid];
    }
#pragma unroll 1
    for (int m = 0; m < 64; m++)
        q_s[m * 256 + tid] = g_Qn[(((size_t)b * 64 + m) << 16) + n];
    __syncthreads();

    float dot = 0.f;
#pragma unroll 4
    for (int m = 0; m < 64; m++) dot += q_s[m * 256 + tid] * ks_s[m];
    float denom = 1.f / (65536.f + dot);

    ull acc[32];
    const ulonglong2* wv2 = (const ulonglong2*)wv_s;
#pragma unroll
    for (int j = 0; j < 16; j++) {
        ulonglong2 w = wv2[j];
        acc[2 * j] = w.x; acc[2 * j + 1] = w.y;
    }
#pragma unroll 4
    for (int m = 0; m < 64; m++) {
        ull qm = bcast2(q_s[m * 256 + tid]);
        const ulonglong2* w2 = (const ulonglong2*)(m2_s + m * 64);
#pragma unroll
        for (int j = 0; j < 16; j++) {
            ulonglong2 w = w2[j];
            fma2(acc[2 * j], w.x, qm);
            fma2(acc[2 * j + 1], w.y, qm);
        }
    }
#pragma unroll
    for (int j = 0; j < 32; j++) {
        float2 f = unpack2(acc[j]);
        g_attn[(((size_t)b * 64 + 2 * j) << 16) + n]     = f.x * denom + __ldg(&br[2 * j]);
        g_attn[(((size_t)b * 64 + 2 * j + 1) << 16) + n] = f.y * denom + __ldg(&br[2 * j + 1]);
    }
}

// ---------------------------------------------------------------------------
// conv3x3 via mma.sync fp16 m16n8k16.
// Block: 8-row band x 128-px x-half x ALL 64 outs. 256 thr (8 warps).
// 2 rows per iteration: warps 0-3 -> row t (32-px quarters), warps 4-7 -> row t+1.
// A smem: 6-slot row ring, [px 130][40 words] fp16x2, word = kc*8+tig*2+s
//         packs ch = kc*16+2tig+8s (+0,+1). px stride 40 -> LDS.64 conflict-free.
// B smem: 36 chunks x [n 64][tig 4][s 2] words (2KB/chunk).
// smem: bias 256 | B 73728 | A 6*20800=124800  => 198784 B
#define CB_OFF   256
#define CA_OFF   73984
#define CA_SLOT  20800
#define CV_SMEM  198784

__device__ __forceinline__ void cv_stage_row(char* smem, int slot,
                                             const float* __restrict__ src,
                                             int b, int gy, int x0, int tid) {
    uint32_t* dstw = (uint32_t*)(smem + CA_OFF + slot * CA_SLOT);
    if ((unsigned)gy < 256u) {
        const float* sp = src + ((size_t)b << 22) + ((size_t)gy << 8);
        for (int i = tid; i < 4160; i += 256) {
            int p  = i / 130;                 // channel pair 0..31
            int hx = i - p * 130;             // 0..129
            int gx = x0 - 1 + hx;
            float f0 = 0.f, f1 = 0.f;
            if ((unsigned)gx < 256u) {
                f0 = __ldg(sp + ((size_t)(2 * p) << 16) + gx);
                f1 = __ldg(sp + ((size_t)(2 * p + 1) << 16) + gx);
            }
            __half2 h = __float22half2_rn(make_float2(f0, f1));
            int w = (p >> 3) * 8 + (p & 3) * 2 + ((p >> 2) & 1);
            dstw[hx * 40 + w] = *(uint32_t*)&h;
        }
    } else {
        for (int i = tid; i < 4160; i += 256) {
            int p  = i / 130;
            int hx = i - p * 130;
            int w = (p >> 3) * 8 + (p & 3) * 2 + ((p >> 2) & 1);
            dstw[hx * 40 + w] = 0u;
        }
    }
}

__global__ void __launch_bounds__(256, 1)
k_conv_mma(const float* __restrict__ src, const float* __restrict__ bias,
           float* __restrict__ dst, const float* __restrict__ xres,
           int fuse, int convIdx) {
    extern __shared__ char smc[];
    const int tid = threadIdx.x;
    const int wid = tid >> 5;
    const int lane = tid & 31;
    const int g   = lane >> 2;
    const int tig = lane & 3;

    const int xh   = blockIdx.x & 1;
    const int band = (blockIdx.x >> 1) & 31;
    const int b    = blockIdx.x >> 6;
    const int y0   = band << 3;
    const int x0   = xh << 7;

    if (tid < 64) ((float*)smc)[tid] = bias[tid];
    {
        const uint4* bsrc = (const uint4*)(g_convB + convIdx * 18432);
        uint4* bdst = (uint4*)(smc + CB_OFF);
        for (int q = tid; q < 4608; q += 256) bdst[q] = bsrc[q];
    }

    // prologue: rows y0-1 .. y0+2 ; slot(r) = (r+1) % 6
    cv_stage_row(smc, (y0)     % 6, src, b, y0 - 1, x0, tid);
    cv_stage_row(smc, (y0 + 1) % 6, src, b, y0,     x0, tid);
    cv_stage_row(smc, (y0 + 2) % 6, src, b, y0 + 1, x0, tid);
    cv_stage_row(smc, (y0 + 3) % 6, src, b, y0 + 2, x0, tid);
    __syncthreads();

    const int rsel = wid >> 2;            // which of 2 rows this warp handles
    const int px0  = (wid & 3) << 5;      // 32-px quarter

    for (int t = 0; t < 8; t += 2) {
        const int y = y0 + t + rsel;

        float acc[16][4];
#pragma unroll
        for (int i = 0; i < 16; i++)
#pragma unroll
            for (int r = 0; r < 4; r++) acc[i][r] = 0.f;

#pragma unroll
        for (int ky = 0; ky < 3; ky++) {
            // input row for tap ky is y+ky-1 -> slot ((y+ky-1)+1)%6
            const char* aSlot = smc + CA_OFF + ((y + ky) % 6) * CA_SLOT;
#pragma unroll
            for (int kx = 0; kx < 3; kx++) {
                const char* aBase = aSlot + ((px0 + kx + g) * 40 + tig * 2) * 4;
                const char* bTap  = smc + CB_OFF + (ky * 3 + kx) * 8192
                                    + (g * 8 + tig * 2) * 4;
#pragma unroll
                for (int kc = 0; kc < 4; kc++) {
                    uint2 A0 = *(const uint2*)(aBase + kc * 32);
                    uint2 A1 = *(const uint2*)(aBase + 8  * 160 + kc * 32);
                    uint2 A2 = *(const uint2*)(aBase + 16 * 160 + kc * 32);
                    uint2 A3 = *(const uint2*)(aBase + 24 * 160 + kc * 32);
                    const char* bc = bTap + kc * 2048;
#pragma unroll
                    for (int nf = 0; nf < 8; nf++) {
                        uint2 B = *(const uint2*)(bc + nf * 256);
                        mma_fp16(acc[nf],     A0.x, A1.x, A0.y, A1.y, B.x, B.y);
                        mma_fp16(acc[8 + nf], A2.x, A3.x, A2.y, A3.y, B.x, B.y);
                    }
                }
            }
        }

        // epilogue
        {
            const float* bs = (const float*)smc;
            const size_t rowOff = ((size_t)b << 22) + ((size_t)y << 8);
            const int pxb = x0 + px0 + g;
#pragma unroll
            for (int nf = 0; nf < 8; nf++) {
                int o0 = nf * 8 + tig * 2;
                float b0v = bs[o0], b1v = bs[o0 + 1];
#pragma unroll
                for (int mf = 0; mf < 2; mf++) {
                    int pxl = pxb + mf * 16;
                    size_t i00 = rowOff + ((size_t)o0 << 16) + pxl;
                    size_t i01 = rowOff + ((size_t)(o0 + 1) << 16) + pxl;
                    float v00 = acc[mf * 8 + nf][0] + b0v;
                    float v01 = acc[mf * 8 + nf][1] + b1v;
                    float v10 = acc[mf * 8 + nf][2] + b0v;
                    float v11 = acc[mf * 8 + nf][3] + b1v;
                    if (fuse) {
                        float xa = xres[i00],     xb = xres[i01];
                        float xc = xres[i00 + 8], xd = xres[i01 + 8];
                        dst[i00]     = v00 * xa + xa;
                        dst[i01]     = v01 * xb + xb;
                        dst[i00 + 8] = v10 * xc + xc;
                        dst[i01 + 8] = v11 * xd + xd;
                    } else {
                        dst[i00]     = v00;
                        dst[i01]     = v01;
                        dst[i00 + 8] = v10;
                        dst[i01 + 8] = v11;
                    }
                }
            }
        }

        // stage rows y0+t+3, y0+t+4 into free slots
        if (t < 6) {
            cv_stage_row(smc, (y0 + t + 4) % 6, src, b, y0 + t + 3, x0, tid);
            cv_stage_row(smc, (y0 + t + 5) % 6, src, b, y0 + t + 4, x0, tid);
        }
        __syncthreads();
    }
}

// ---------------------------------------------------------------------------
extern "C" void kernel_launch(void* const* d_in, const int* in_sizes, int n_in,
                              void* d_out, int out_size) {
    const float* x  = (const float*)d_in[0];
    const float* Wq = (const float*)d_in[1];
    const float* bq = (const float*)d_in[2];
    const float* Wk = (const float*)d_in[3];
    const float* bk = (const float*)d_in[4];
    const float* Wv = (const float*)d_in[5];
    const float* bv = (const float*)d_in[6];
    const float* Wr = (const float*)d_in[7];
    const float* br = (const float*)d_in[8];
    const float* W1 = (const float*)d_in[9];
    const float* b1 = (const float*)d_in[10];
    const float* W2 = (const float*)d_in[11];
    const float* b2 = (const float*)d_in[12];
    float* out = (float*)d_out;

    cudaFuncSetAttribute(k_qkv,      cudaFuncAttributeMaxDynamicSharedMemorySize, SMEM_QKV);
    cudaFuncSetAttribute(k_attn,     cudaFuncAttributeMaxDynamicSharedMemorySize, SMEM_ATTN);
    cudaFuncSetAttribute(k_conv_mma, cudaFuncAttributeMaxDynamicSharedMemorySize, CV_SMEM);

    void *p_attn, *p_t1;
    cudaGetSymbolAddress(&p_attn, g_attn);
    cudaGetSymbolAddress(&p_t1, g_t1);

    k_zero<<<128, 256>>>();
    k_prepB<<<144, 256>>>(W1, W2);
    k_qkv<<<2048, 256, SMEM_QKV>>>(x, Wq, bq, Wk, bk, Wv, bv);
    k_fin<<<8, 256>>>(Wr);
    k_attn<<<2048, 256, SMEM_ATTN>>>(br);
    k_conv_mma<<<512, 256, CV_SMEM>>>((const float*)p_attn, b1, (float*)p_t1,
                                      nullptr, 0, 0);
    k_conv_mma<<<512, 256, CV_SMEM>>>((const float*)p_t1, b2, out, x, 1, 1);
}

// round 6
// speedup vs baseline: 3.3047x; 1.6968x over previous
#include <cuda_runtime.h>
#include <cuda_fp16.h>
#include <cstdint>

// ---------------------------------------------------------------------------
// HydraAttention_v2 — fully tensorized (mma.sync fp16 m16n8k16), fp16 packed
// fragment-layout intermediates. B=8, C=64, H=W=256, N=65536
// Packed word layout (everywhere): word w = kc*8 + tig*2 + s at a pixel packs
// channels (16kc + 2tig + 8s, +1) as half2 — directly loadable as mma A-frags.
// ---------------------------------------------------------------------------

#define BATCH 8
#define CH    64
#define NPIX  65536

typedef unsigned long long ull;

__device__ uint32_t g_QnP[BATCH * NPIX * 32];    // packed fp16 Qn
__device__ uint32_t g_attnP[BATCH * NPIX * 32];  // packed fp16 attn
__device__ uint32_t g_t1P[BATCH * NPIX * 32];    // packed fp16 conv1 out
__device__ float    g_ksum[BATCH * CH];
__device__ float    g_vsum[BATCH * CH];
__device__ float    g_aggkv[BATCH * CH * CH];
__device__ float    g_wrvs[BATCH * CH];
__device__ uint32_t g_M2h[BATCH * 2048];         // packed fp16 M2 B-frags
__device__ uint32_t g_qkvB[6144];                // packed fp16 QKV weights
__device__ uint32_t g_convB[2 * 36 * 64 * 8];    // packed fp16 conv weights

// ---- helpers ----------------------------------------------------------------
__device__ __forceinline__ ull bcast2(float v) {
    ull r; asm("mov.b64 %0, {%1, %1};" : "=l"(r) : "f"(v)); return r;
}
__device__ __forceinline__ ull pk2(float a, float b) {
    ull r; asm("mov.b64 %0, {%1, %2};" : "=l"(r) : "f"(a), "f"(b)); return r;
}
__device__ __forceinline__ void fma2(ull& d, ull a, ull b) {
    asm("fma.rn.f32x2 %0, %1, %2, %0;" : "+l"(d) : "l"(a), "l"(b));
}
__device__ __forceinline__ float2 unpack2(ull v) {
    float2 f; asm("mov.b64 {%0, %1}, %2;" : "=f"(f.x), "=f"(f.y) : "l"(v)); return f;
}
__device__ __forceinline__ void mma_fp16(float c[4], uint32_t a0, uint32_t a1,
                                         uint32_t a2, uint32_t a3,
                                         uint32_t b0, uint32_t b1) {
    asm volatile(
        "mma.sync.aligned.m16n8k16.row.col.f32.f16.f16.f32 "
        "{%0,%1,%2,%3}, {%4,%5,%6,%7}, {%8,%9}, {%0,%1,%2,%3};"
        : "+f"(c[0]), "+f"(c[1]), "+f"(c[2]), "+f"(c[3])
        : "r"(a0), "r"(a1), "r"(a2), "r"(a3), "r"(b0), "r"(b1));
}
__device__ __forceinline__ uint32_t h2pack(float a, float b) {
    __half2 h = __float22half2_rn(make_float2(a, b));
    return *(uint32_t*)&h;
}
__device__ __forceinline__ float2 h2up(uint32_t w) {
    __half2 h = *(__half2*)&w;
    return __half22float2(h);
}

// ---------------------------------------------------------------------------
// prep: conv weights, qkv weights (packed fp16), zero accumulators
__global__ void k_prep(const float* __restrict__ Wq, const float* __restrict__ Wk,
                       const float* __restrict__ Wv,
                       const float* __restrict__ W1, const float* __restrict__ W2) {
    int i = blockIdx.x * 256 + threadIdx.x;
    if (i < 36864) {
        // conv B frags: chunk = tap*4+kc; word packs ch = kc*16+2tig+8s (+1)
        int f = i;
        int conv = f / 18432;
        int r    = f % 18432;
        int chunk = r >> 9;
        int w     = r & 511;
        int n   = w >> 3;
        int ww  = w & 7;
        int tig = ww >> 1, s = ww & 1;
        int tap = chunk >> 2, kc = chunk & 3;
        int ch = kc * 16 + 2 * tig + 8 * s;
        const float* W = conv ? W2 : W1;
        g_convB[f] = h2pack(W[n * 576 + ch * 9 + tap], W[n * 576 + (ch + 1) * 9 + tap]);
    } else if (i < 43008) {
        // qkv B: word = ((kc*24+nf)*64 + g*8 + tig*2 + s); col n = 8nf+g
        int f = i - 36864;
        int s = f & 1, tig = (f >> 1) & 3, g = (f >> 3) & 7;
        int nf = (f >> 6) % 24, kc = f / (64 * 24);
        int n = nf * 8 + g;
        int ch = kc * 16 + tig * 2 + s * 8;
        const float* W; int row;
        if (n < 64)       { W = Wq; row = n; }
        else if (n < 96)  { W = Wv; row = n - 64; }
        else if (n < 160) { W = Wk; row = n - 96; }
        else              { W = Wv; row = n - 128; }
        g_qkvB[f] = h2pack(W[row * 64 + ch], W[row * 64 + ch + 1]);
    } else if (i < 43520) {
        int j = i - 43008;
        g_ksum[j] = 0.f; g_vsum[j] = 0.f;
    } else if (i < 76288) {
        g_aggkv[i - 43520] = 0.f;
    }
}

// ---------------------------------------------------------------------------
// k_qkv: 128-px blocks. GEMM [128px x 192] via mma; norm Q,K; write Qn packed;
// in-block ksum/vsum/aggkv with atomics.
#define QK_XA   0            // 128*40*4 = 20480
#define QK_B    20480        // 6144*4   = 24576
#define QK_KS   45056        // 64*129*4 = 33024   k_s [m][129]
#define QK_VS   78080        // 128*68*4 = 34816   v_s [px][68]
#define QK_QN   112896       // 128*33*4 = 16896   qn  [px][33]
#define QK_SMEM 129792

__global__ void __launch_bounds__(256, 1)
k_qkv(const float* __restrict__ x, const float* __restrict__ bq,
      const float* __restrict__ bk, const float* __restrict__ bv) {
    extern __shared__ char sm[];
    uint32_t* Bw  = (uint32_t*)(sm + QK_B);
    float*    k_s = (float*)(sm + QK_KS);
    float*    v_s = (float*)(sm + QK_VS);
    uint32_t* qn  = (uint32_t*)(sm + QK_QN);

    const int tid = threadIdx.x;
    const int b  = blockIdx.x >> 9;
    const int n0 = (blockIdx.x & 511) << 7;

    for (int i = tid; i < 6144; i += 256) Bw[i] = g_qkvB[i];

    const float* xb = x + ((size_t)b << 22) + n0;
    {
        uint32_t* xa = (uint32_t*)(sm + QK_XA);
        for (int i = tid; i < 4096; i += 256) {
            int px = i & 127, p = i >> 7;
            float f0 = __ldg(xb + ((size_t)(2 * p) << 16) + px);
            float f1 = __ldg(xb + ((size_t)(2 * p + 1) << 16) + px);
            int kc = p >> 3, t3 = p & 7;
            int w = kc * 8 + (t3 & 3) * 2 + (t3 >> 2);
            xa[px * 40 + w] = h2pack(f0, f1);
        }
    }
    __syncthreads();

    const int wid = tid >> 5, lane = tid & 31;
    const int g = lane >> 2, tig = lane & 3;
    const int pxq = wid & 3, nh = wid >> 2;
    const int px0 = pxq << 5;

    float acc[2][12][4];
#pragma unroll
    for (int mf = 0; mf < 2; mf++)
#pragma unroll
        for (int nf = 0; nf < 12; nf++)
#pragma unroll
            for (int r = 0; r < 4; r++) acc[mf][nf][r] = 0.f;

#pragma unroll
    for (int kc = 0; kc < 4; kc++) {
        uint2 A[2][2];
#pragma unroll
        for (int mf = 0; mf < 2; mf++) {
            const char* ab = sm + QK_XA + ((px0 + mf * 16 + g) * 40 + tig * 2) * 4;
            A[mf][0] = *(const uint2*)(ab + kc * 32);
            A[mf][1] = *(const uint2*)(ab + 8 * 160 + kc * 32);
        }
#pragma unroll
        for (int nf = 0; nf < 12; nf++) {
            int nfg = nh * 12 + nf;
            uint2 Bv = *(const uint2*)((const char*)Bw +
                        ((kc * 24 + nfg) * 64 + g * 8 + tig * 2) * 4);
            mma_fp16(acc[0][nf], A[0][0].x, A[0][1].x, A[0][0].y, A[0][1].y, Bv.x, Bv.y);
            mma_fp16(acc[1][nf], A[1][0].x, A[1][1].x, A[1][0].y, A[1][1].y, Bv.x, Bv.y);
        }
    }

    // biases
#pragma unroll
    for (int nf = 0; nf < 12; nf++) {
        float2 bb;
        if (nh == 0) bb = (nf < 8) ? *(const float2*)(bq + nf * 8 + tig * 2)
                                   : *(const float2*)(bv + (nf - 8) * 8 + tig * 2);
        else         bb = (nf < 8) ? *(const float2*)(bk + nf * 8 + tig * 2)
                                   : *(const float2*)(bv + 32 + (nf - 8) * 8 + tig * 2);
#pragma unroll
        for (int mf = 0; mf < 2; mf++) {
            acc[mf][nf][0] += bb.x; acc[mf][nf][1] += bb.y;
            acc[mf][nf][2] += bb.x; acc[mf][nf][3] += bb.y;
        }
    }

    // normalize Q (nh0) / K (nh1), write Qn packed / Kn fp32 / V fp32
#pragma unroll
    for (int mf = 0; mf < 2; mf++) {
        float ss0 = 0.f, ss1 = 0.f;
#pragma unroll
        for (int nf = 0; nf < 8; nf++) {
            ss0 += acc[mf][nf][0] * acc[mf][nf][0] + acc[mf][nf][1] * acc[mf][nf][1];
            ss1 += acc[mf][nf][2] * acc[mf][nf][2] + acc[mf][nf][3] * acc[mf][nf][3];
        }
        ss0 += __shfl_xor_sync(0xffffffffu, ss0, 1);
        ss0 += __shfl_xor_sync(0xffffffffu, ss0, 2);
        ss1 += __shfl_xor_sync(0xffffffffu, ss1, 1);
        ss1 += __shfl_xor_sync(0xffffffffu, ss1, 2);
        float inv0 = rsqrtf(ss0), inv1 = rsqrtf(ss1);
        const int pxA = px0 + mf * 16 + g, pxB = pxA + 8;

        if (nh == 0) {
#pragma unroll
            for (int nf = 0; nf < 8; nf++) {
                int w = (nf >> 1) * 8 + tig * 2 + (nf & 1);
                qn[pxA * 33 + w] = h2pack(acc[mf][nf][0] * inv0, acc[mf][nf][1] * inv0);
                qn[pxB * 33 + w] = h2pack(acc[mf][nf][2] * inv1, acc[mf][nf][3] * inv1);
            }
        } else {
#pragma unroll
            for (int nf = 0; nf < 8; nf++) {
                int m = nf * 8 + tig * 2;
                k_s[m * 129 + pxA]       = acc[mf][nf][0] * inv0;
                k_s[(m + 1) * 129 + pxA] = acc[mf][nf][1] * inv0;
                k_s[m * 129 + pxB]       = acc[mf][nf][2] * inv1;
                k_s[(m + 1) * 129 + pxB] = acc[mf][nf][3] * inv1;
            }
        }
#pragma unroll
        for (int nf = 8; nf < 12; nf++) {
            int c = (nh ? 32 : 0) + (nf - 8) * 8 + tig * 2;
            *(float2*)&v_s[pxA * 68 + c] = make_float2(acc[mf][nf][0], acc[mf][nf][1]);
            *(float2*)&v_s[pxB * 68 + c] = make_float2(acc[mf][nf][2], acc[mf][nf][3]);
        }
    }
    __syncthreads();

    // Qn bulk copy to global (coalesced)
    {
        uint32_t* gq = g_QnP + (((size_t)b << 16) + n0) * 32;
        for (int j = tid; j < 4096; j += 256)
            gq[j] = qn[(j >> 5) * 33 + (j & 31)];
    }

    // ksum / vsum
    if (tid < 128) {
        int row = tid & 63;
        float s = 0.f;
        if (tid < 64) {
            for (int i = 0; i < 128; i++) {
                int p = (i + tid) & 127;
                s += k_s[row * 129 + p];
            }
            atomicAdd(&g_ksum[b * 64 + row], s);
        } else {
            for (int i = 0; i < 128; i++) {
                int p = (i + tid) & 127;
                s += v_s[p * 68 + row];
            }
            atomicAdd(&g_vsum[b * 64 + row], s);
        }
    }

    // aggkv[m][c] partial (4x4 per thread, packed fp32x2)
    {
        const int m0 = (tid >> 4) << 2;
        const int c0 = (tid & 15) << 2;
        ull a2[4][2];
#pragma unroll
        for (int i = 0; i < 4; i++) { a2[i][0] = 0; a2[i][1] = 0; }
        for (int it = 0; it < 128; it++) {
            int p = (it + tid) & 127;
            float4 vv = *(const float4*)&v_s[p * 68 + c0];
            ull v01 = pk2(vv.x, vv.y), v23 = pk2(vv.z, vv.w);
#pragma unroll
            for (int i = 0; i < 4; i++) {
                ull kb = bcast2(k_s[(m0 + i) * 129 + p]);
                fma2(a2[i][0], kb, v01);
                fma2(a2[i][1], kb, v23);
            }
        }
#pragma unroll
        for (int i = 0; i < 4; i++) {
            float2 f0 = unpack2(a2[i][0]), f1 = unpack2(a2[i][1]);
            float* dp = &g_aggkv[((size_t)b * 64 + m0 + i) * 64 + c0];
            atomicAdd(dp + 0, f0.x); atomicAdd(dp + 1, f0.y);
            atomicAdd(dp + 2, f1.x); atomicAdd(dp + 3, f1.y);
        }
    }
}

// ---------------------------------------------------------------------------
// k_fin: wrvs = Wr·vsum ; M2[m][o] = sum_c Wr[o][c]·agg[m][c] -> packed fp16
__global__ void __launch_bounds__(256, 1)
k_fin(const float* __restrict__ Wr) {
    __shared__ float a_s[4096];
    __shared__ float w_s[4096];
    __shared__ float vs_s[64];

    int b = blockIdx.x;
    int tid = threadIdx.x;

    for (int idx = tid; idx < 4096; idx += 256) {
        a_s[idx] = g_aggkv[b * 4096 + idx];
        int o = idx & 63, c = idx >> 6;
        w_s[c * 64 + o] = Wr[o * 64 + c];
    }
    if (tid < 64) vs_s[tid] = g_vsum[b * 64 + tid];
    __syncthreads();

    int o = tid & 63, mg = tid >> 6;
    if (mg == 0) {
        float s = 0.f;
#pragma unroll 8
        for (int c = 0; c < 64; c++) s += w_s[c * 64 + o] * vs_s[c];
        g_wrvs[b * 64 + o] = s;
    }
    int nf = o >> 3, gg = o & 7;
#pragma unroll 1
    for (int m = mg * 16; m < mg * 16 + 16; m += 2) {
        float t0 = 0.f, t1 = 0.f;
#pragma unroll 8
        for (int c = 0; c < 64; c++) {
            t0 += w_s[c * 64 + o] * a_s[m * 64 + c];
            t1 += w_s[c * 64 + o] * a_s[(m + 1) * 64 + c];
        }
        int kc = m >> 4, r = m & 15;
        int s2 = r >> 3, tg = (r & 7) >> 1;
        g_M2h[b * 2048 + ((kc * 8 + nf) * 64 + gg * 8 + tg * 2 + s2)] = h2pack(t0, t1);
    }
}

// ---------------------------------------------------------------------------
// k_attn: 128-px blocks; GEMM Qn[128x64m] x M2h[64m x 64o] via mma
#define AT_QN   0        // 128*40*4 = 20480
#define AT_M2   20480    // 8192
#define AT_KS   28672
#define AT_WV   28928
#define AT_BR   29184
#define AT_SMEM 29440

__global__ void __launch_bounds__(256, 1)
k_attn(const float* __restrict__ br) {
    extern __shared__ char sm[];
    uint32_t* m2  = (uint32_t*)(sm + AT_M2);
    float*    ks  = (float*)(sm + AT_KS);
    float*    wv  = (float*)(sm + AT_WV);
    float*    brs = (float*)(sm + AT_BR);

    const int tid = threadIdx.x;
    const int b  = blockIdx.x >> 9;
    const int n0 = (blockIdx.x & 511) << 7;

    {
        const uint4* gq = (const uint4*)(g_QnP + (((size_t)b << 16) + n0) * 32);
        for (int i = tid; i < 1024; i += 256) {
            int px = i >> 3, q4 = i & 7;
            *(uint4*)(sm + (px * 40 + q4 * 4) * 4) = __ldg(gq + px * 8 + q4);
        }
    }
    for (int i = tid; i < 2048; i += 256) m2[i] = g_M2h[b * 2048 + i];
    if (tid < 64) {
        ks[tid]  = g_ksum[b * 64 + tid] + 1e-6f;
        wv[tid]  = g_wrvs[b * 64 + tid];
        brs[tid] = __ldg(&br[tid]);
    }
    __syncthreads();

    const int wid = tid >> 5, lane = tid & 31;
    const int g = lane >> 2, tig = lane & 3;
    const int px0 = wid << 4;

    float acc[8][4];
#pragma unroll
    for (int nf = 0; nf < 8; nf++)
#pragma unroll
        for (int r = 0; r < 4; r++) acc[nf][r] = 0.f;
    float dot0 = 0.f, dot1 = 0.f;

#pragma unroll
    for (int kc = 0; kc < 4; kc++) {
        const char* ab = sm + ((px0 + g) * 40 + tig * 2) * 4;
        uint2 A0 = *(const uint2*)(ab + kc * 32);
        uint2 A1 = *(const uint2*)(ab + 8 * 160 + kc * 32);
        float2 ka = *(const float2*)&ks[kc * 16 + tig * 2];
        float2 kb = *(const float2*)&ks[kc * 16 + tig * 2 + 8];
        float2 f;
        f = h2up(A0.x); dot0 += f.x * ka.x + f.y * ka.y;
        f = h2up(A0.y); dot0 += f.x * kb.x + f.y * kb.y;
        f = h2up(A1.x); dot1 += f.x * ka.x + f.y * ka.y;
        f = h2up(A1.y); dot1 += f.x * kb.x + f.y * kb.y;
#pragma unroll
        for (int nf = 0; nf < 8; nf++) {
            uint2 Bv = *(const uint2*)((const char*)m2 +
                        ((kc * 8 + nf) * 64 + g * 8 + tig * 2) * 4);
            mma_fp16(acc[nf], A0.x, A1.x, A0.y, A1.y, Bv.x, Bv.y);
        }
    }
    dot0 += __shfl_xor_sync(0xffffffffu, dot0, 1);
    dot0 += __shfl_xor_sync(0xffffffffu, dot0, 2);
    dot1 += __shfl_xor_sync(0xffffffffu, dot1, 1);
    dot1 += __shfl_xor_sync(0xffffffffu, dot1, 2);
    float den0 = 1.f / (65536.f + dot0);
    float den1 = 1.f / (65536.f + dot1);

    uint32_t* ga = g_attnP + (((size_t)b << 16) + n0) * 32;
#pragma unroll
    for (int nf = 0; nf < 8; nf++) {
        int o = nf * 8 + tig * 2;
        int w = (nf >> 1) * 8 + tig * 2 + (nf & 1);
        float v0 = brs[o]     + den0 * (wv[o]     + acc[nf][0]);
        float v1 = brs[o + 1] + den0 * (wv[o + 1] + acc[nf][1]);
        float v2 = brs[o]     + den1 * (wv[o]     + acc[nf][2]);
        float v3 = brs[o + 1] + den1 * (wv[o + 1] + acc[nf][3]);
        ga[(px0 + g) * 32 + w]     = h2pack(v0, v1);
        ga[(px0 + g + 8) * 32 + w] = h2pack(v2, v3);
    }
}

// ---------------------------------------------------------------------------
// conv3x3 via mma.sync fp16, input/weights packed fp16. Same structure as R5
// but staging is a pure uint4 copy (input already packed fp16 in global).
#define CB_OFF   256
#define CA_OFF   73984
#define CA_SLOT  20800
#define CV_SMEM  198784

__device__ __forceinline__ void cv_stage_row(char* smem, int slot,
                                             const uint4* __restrict__ src,
                                             int b, int gy, int x0, int tid) {
    char* dstc = smem + CA_OFF + slot * CA_SLOT;
    if ((unsigned)gy < 256u) {
        const uint4* sp = src + (((size_t)(b * 65536 + gy * 256)) << 3);
        for (int i = tid; i < 1040; i += 256) {
            int px = i >> 3, q4 = i & 7;
            int gx = x0 - 1 + px;
            uint4 v = make_uint4(0u, 0u, 0u, 0u);
            if ((unsigned)gx < 256u) v = __ldg(sp + (gx << 3) + q4);
            *(uint4*)(dstc + (px * 40 + q4 * 4) * 4) = v;
        }
    } else {
        for (int i = tid; i < 1040; i += 256) {
            int px = i >> 3, q4 = i & 7;
            *(uint4*)(dstc + (px * 40 + q4 * 4) * 4) = make_uint4(0u, 0u, 0u, 0u);
        }
    }
}

__global__ void __launch_bounds__(256, 1)
k_conv_mma(const uint4* __restrict__ srcP, const float* __restrict__ bias,
           float* __restrict__ dstF, uint32_t* __restrict__ dstP,
           const float* __restrict__ xres, int fuse, int convIdx) {
    extern __shared__ char smc[];
    const int tid = threadIdx.x;
    const int wid = tid >> 5;
    const int lane = tid & 31;
    const int g   = lane >> 2;
    const int tig = lane & 3;

    const int xh   = blockIdx.x & 1;
    const int band = (blockIdx.x >> 1) & 31;
    const int b    = blockIdx.x >> 6;
    const int y0   = band << 3;
    const int x0   = xh << 7;

    if (tid < 64) ((float*)smc)[tid] = bias[tid];
    {
        const uint4* bsrc = (const uint4*)(g_convB + convIdx * 18432);
        uint4* bdst = (uint4*)(smc + CB_OFF);
        for (int q = tid; q < 4608; q += 256) bdst[q] = bsrc[q];
    }

    cv_stage_row(smc, (y0)     % 6, srcP, b, y0 - 1, x0, tid);
    cv_stage_row(smc, (y0 + 1) % 6, srcP, b, y0,     x0, tid);
    cv_stage_row(smc, (y0 + 2) % 6, srcP, b, y0 + 1, x0, tid);
    cv_stage_row(smc, (y0 + 3) % 6, srcP, b, y0 + 2, x0, tid);
    __syncthreads();

    const int rsel = wid >> 2;
    const int px0  = (wid & 3) << 5;

    for (int t = 0; t < 8; t += 2) {
        const int y = y0 + t + rsel;

        float acc[16][4];
#pragma unroll
        for (int i = 0; i < 16; i++)
#pragma unroll
            for (int r = 0; r < 4; r++) acc[i][r] = 0.f;

#pragma unroll
        for (int ky = 0; ky < 3; ky++) {
            const char* aSlot = smc + CA_OFF + ((y + ky) % 6) * CA_SLOT;
#pragma unroll
            for (int kx = 0; kx < 3; kx++) {
                const char* aBase = aSlot + ((px0 + kx + g) * 40 + tig * 2) * 4;
                const char* bTap  = smc + CB_OFF + (ky * 3 + kx) * 8192
                                    + (g * 8 + tig * 2) * 4;
#pragma unroll
                for (int kc = 0; kc < 4; kc++) {
                    uint2 A0 = *(const uint2*)(aBase + kc * 32);
                    uint2 A1 = *(const uint2*)(aBase + 8  * 160 + kc * 32);
                    uint2 A2 = *(const uint2*)(aBase + 16 * 160 + kc * 32);
                    uint2 A3 = *(const uint2*)(aBase + 24 * 160 + kc * 32);
                    const char* bc = bTap + kc * 2048;
#pragma unroll
                    for (int nf = 0; nf < 8; nf++) {
                        uint2 B = *(const uint2*)(bc + nf * 256);
                        mma_fp16(acc[nf],     A0.x, A1.x, A0.y, A1.y, B.x, B.y);
                        mma_fp16(acc[8 + nf], A2.x, A3.x, A2.y, A3.y, B.x, B.y);
                    }
                }
            }
        }

        {
            const float* bs = (const float*)smc;
            const int pxb = x0 + px0 + g;
            if (fuse) {
                const size_t rowOff = ((size_t)b << 22) + ((size_t)y << 8);
#pragma unroll
                for (int nf = 0; nf < 8; nf++) {
                    int o0 = nf * 8 + tig * 2;
                    float b0v = bs[o0], b1v = bs[o0 + 1];
#pragma unroll
                    for (int mf = 0; mf < 2; mf++) {
                        int pxl = pxb + mf * 16;
                        size_t i00 = rowOff + ((size_t)o0 << 16) + pxl;
                        size_t i01 = rowOff + ((size_t)(o0 + 1) << 16) + pxl;
                        float v00 = acc[mf * 8 + nf][0] + b0v;
                        float v01 = acc[mf * 8 + nf][1] + b1v;
                        float v10 = acc[mf * 8 + nf][2] + b0v;
                        float v11 = acc[mf * 8 + nf][3] + b1v;
                        float xa = xres[i00],     xb2 = xres[i01];
                        float xc = xres[i00 + 8], xd = xres[i01 + 8];
                        dstF[i00]     = v00 * xa + xa;
                        dstF[i01]     = v01 * xb2 + xb2;
                        dstF[i00 + 8] = v10 * xc + xc;
                        dstF[i01 + 8] = v11 * xd + xd;
                    }
                }
            } else {
                const size_t rowBase = ((size_t)(b * 65536 + y * 256));
#pragma unroll
                for (int nf = 0; nf < 8; nf++) {
                    int o0 = nf * 8 + tig * 2;
                    float b0v = bs[o0], b1v = bs[o0 + 1];
                    int w = (nf >> 1) * 8 + tig * 2 + (nf & 1);
#pragma unroll
                    for (int mf = 0; mf < 2; mf++) {
                        int pxl = pxb + mf * 16;
                        size_t base = (rowBase + pxl) * 32 + w;
                        dstP[base]          = h2pack(acc[mf * 8 + nf][0] + b0v,
                                                     acc[mf * 8 + nf][1] + b1v);
                        dstP[base + 8 * 32] = h2pack(acc[mf * 8 + nf][2] + b0v,
                                                     acc[mf * 8 + nf][3] + b1v);
                    }
                }
            }
        }

        if (t < 6) {
            cv_stage_row(smc, (y0 + t + 4) % 6, srcP, b, y0 + t + 3, x0, tid);
            cv_stage_row(smc, (y0 + t + 5) % 6, srcP, b, y0 + t + 4, x0, tid);
        }
        __syncthreads();
    }
}

// ---------------------------------------------------------------------------
extern "C" void kernel_launch(void* const* d_in, const int* in_sizes, int n_in,
                              void* d_out, int out_size) {
    const float* x  = (const float*)d_in[0];
    const float* Wq = (const float*)d_in[1];
    const float* bq = (const float*)d_in[2];
    const float* Wk = (const float*)d_in[3];
    const float* bk = (const float*)d_in[4];
    const float* Wv = (const float*)d_in[5];
    const float* bv = (const float*)d_in[6];
    const float* Wr = (const float*)d_in[7];
    const float* br = (const float*)d_in[8];
    const float* W1 = (const float*)d_in[9];
    const float* b1 = (const float*)d_in[10];
    const float* W2 = (const float*)d_in[11];
    const float* b2 = (const float*)d_in[12];
    float* out = (float*)d_out;

    cudaFuncSetAttribute(k_qkv,      cudaFuncAttributeMaxDynamicSharedMemorySize, QK_SMEM);
    cudaFuncSetAttribute(k_attn,     cudaFuncAttributeMaxDynamicSharedMemorySize, AT_SMEM);
    cudaFuncSetAttribute(k_conv_mma, cudaFuncAttributeMaxDynamicSharedMemorySize, CV_SMEM);

    void *p_attnP, *p_t1P;
    cudaGetSymbolAddress(&p_attnP, g_attnP);
    cudaGetSymbolAddress(&p_t1P, g_t1P);

    k_prep<<<298, 256>>>(Wq, Wk, Wv, W1, W2);
    k_qkv<<<4096, 256, QK_SMEM>>>(x, bq, bk, bv);
    k_fin<<<8, 256>>>(Wr);
    k_attn<<<4096, 256, AT_SMEM>>>(br);
    k_conv_mma<<<512, 256, CV_SMEM>>>((const uint4*)p_attnP, b1, nullptr,
                                      (uint32_t*)p_t1P, nullptr, 0, 0);
    k_conv_mma<<<512, 256, CV_SMEM>>>((const uint4*)p_t1P, b2, out,
                                      nullptr, x, 1, 1);
}

// round 7
// speedup vs baseline: 4.7359x; 1.4331x over previous
#include <cuda_runtime.h>
#include <cuda_fp16.h>
#include <cstdint>

// ---------------------------------------------------------------------------
// HydraAttention_v2 — fully tensorized (mma.sync fp16 m16n8k16), fp16 packed
// fragment-layout intermediates. aggkv also via mma + scratch reduction.
// B=8, C=64, H=W=256, N=65536
// ---------------------------------------------------------------------------

#define BATCH 8
#define CH    64
#define NPIX  65536

typedef unsigned long long ull;

__device__ uint32_t g_QnP[BATCH * NPIX * 32];    // packed fp16 Qn
__device__ uint32_t g_attnP[BATCH * NPIX * 32];  // packed fp16 attn
__device__ uint32_t g_t1P[BATCH * NPIX * 32];    // conv1 out; BEFORE conv1: qkv aggkv scratch
__device__ float    g_ksum[BATCH * CH];
__device__ float    g_vsum[BATCH * CH];
__device__ float    g_aggkv[BATCH * CH * CH];
__device__ float    g_wrvs[BATCH * CH];
__device__ uint32_t g_M2h[BATCH * 2048];         // packed fp16 M2 B-frags
__device__ uint32_t g_qkvB[6144];                // packed fp16 QKV weights
__device__ uint32_t g_convB[2 * 36 * 64 * 8];    // packed fp16 conv weights

// ---- helpers ----------------------------------------------------------------
__device__ __forceinline__ void mma_fp16(float c[4], uint32_t a0, uint32_t a1,
                                         uint32_t a2, uint32_t a3,
                                         uint32_t b0, uint32_t b1) {
    asm volatile(
        "mma.sync.aligned.m16n8k16.row.col.f32.f16.f16.f32 "
        "{%0,%1,%2,%3}, {%4,%5,%6,%7}, {%8,%9}, {%0,%1,%2,%3};"
        : "+f"(c[0]), "+f"(c[1]), "+f"(c[2]), "+f"(c[3])
        : "r"(a0), "r"(a1), "r"(a2), "r"(a3), "r"(b0), "r"(b1));
}
__device__ __forceinline__ uint32_t h2pack(float a, float b) {
    __half2 h = __float22half2_rn(make_float2(a, b));
    return *(uint32_t*)&h;
}
__device__ __forceinline__ float2 h2up(uint32_t w) {
    __half2 h = *(__half2*)&w;
    return __half22float2(h);
}

// ---------------------------------------------------------------------------
__global__ void k_prep(const float* __restrict__ Wq, const float* __restrict__ Wk,
                       const float* __restrict__ Wv,
                       const float* __restrict__ W1, const float* __restrict__ W2) {
    int i = blockIdx.x * 256 + threadIdx.x;
    if (i < 36864) {
        int f = i;
        int conv = f / 18432;
        int r    = f % 18432;
        int chunk = r >> 9;
        int w     = r & 511;
        int n   = w >> 3;
        int ww  = w & 7;
        int tig = ww >> 1, s = ww & 1;
        int tap = chunk >> 2, kc = chunk & 3;
        int ch = kc * 16 + 2 * tig + 8 * s;
        const float* W = conv ? W2 : W1;
        g_convB[f] = h2pack(W[n * 576 + ch * 9 + tap], W[n * 576 + (ch + 1) * 9 + tap]);
    } else if (i < 43008) {
        int f = i - 36864;
        int s = f & 1, tig = (f >> 1) & 3, g = (f >> 3) & 7;
        int nf = (f >> 6) % 24, kc = f / (64 * 24);
        int n = nf * 8 + g;
        int ch = kc * 16 + tig * 2 + s * 8;
        const float* W; int row;
        if (n < 64)       { W = Wq; row = n; }
        else if (n < 96)  { W = Wv; row = n - 64; }
        else if (n < 160) { W = Wk; row = n - 96; }
        else              { W = Wv; row = n - 128; }
        g_qkvB[f] = h2pack(W[row * 64 + ch], W[row * 64 + ch + 1]);
    } else if (i < 43520) {
        int j = i - 43008;
        g_ksum[j] = 0.f; g_vsum[j] = 0.f;
    }
}

// ---------------------------------------------------------------------------
// k_qkv: 128-px blocks. QKV GEMM via mma; norms; Qn packed out; Kn/V to fp16
// smem; aggkv 64x64x128 GEMM via mma -> per-block partial to scratch (g_t1P).
#define QK_XA   0            // 20480 (x frags; reused as agg staging 64*66*4)
#define QK_B    20480        // 24576
#define QK_KN   45056        // 64*68 words = 17408 B (fp16 [m][px], stride 68 w)
#define QK_V    62464        // 17408
#define QK_QN   79872        // 128*33*4 = 16896
#define QK_SMEM 96768

__global__ void __launch_bounds__(256, 2)
k_qkv(const float* __restrict__ x, const float* __restrict__ bq,
      const float* __restrict__ bk, const float* __restrict__ bv,
      float* __restrict__ gpart) {
    extern __shared__ char sm[];
    uint32_t* Bw  = (uint32_t*)(sm + QK_B);
    __half*   knh = (__half*)(sm + QK_KN);
    __half*   vh  = (__half*)(sm + QK_V);
    uint32_t* qn  = (uint32_t*)(sm + QK_QN);

    const int tid = threadIdx.x;
    const int b  = blockIdx.x >> 9;
    const int n0 = (blockIdx.x & 511) << 7;

    for (int i = tid; i < 6144; i += 256) Bw[i] = g_qkvB[i];

    const float* xb = x + ((size_t)b << 22) + n0;
    {
        uint32_t* xa = (uint32_t*)(sm + QK_XA);
        for (int i = tid; i < 4096; i += 256) {
            int px = i & 127, p = i >> 7;
            float f0 = __ldg(xb + ((size_t)(2 * p) << 16) + px);
            float f1 = __ldg(xb + ((size_t)(2 * p + 1) << 16) + px);
            int kc = p >> 3, t3 = p & 7;
            int w = kc * 8 + (t3 & 3) * 2 + (t3 >> 2);
            xa[px * 40 + w] = h2pack(f0, f1);
        }
    }
    __syncthreads();

    const int wid = tid >> 5, lane = tid & 31;
    const int g = lane >> 2, tig = lane & 3;
    const int pxq = wid & 3, nh = wid >> 2;
    const int px0 = pxq << 5;

    float acc[2][12][4];
#pragma unroll
    for (int mf = 0; mf < 2; mf++)
#pragma unroll
        for (int nf = 0; nf < 12; nf++)
#pragma unroll
            for (int r = 0; r < 4; r++) acc[mf][nf][r] = 0.f;

#pragma unroll
    for (int kc = 0; kc < 4; kc++) {
        uint2 A[2][2];
#pragma unroll
        for (int mf = 0; mf < 2; mf++) {
            const char* ab = sm + QK_XA + ((px0 + mf * 16 + g) * 40 + tig * 2) * 4;
            A[mf][0] = *(const uint2*)(ab + kc * 32);
            A[mf][1] = *(const uint2*)(ab + 8 * 160 + kc * 32);
        }
#pragma unroll
        for (int nf = 0; nf < 12; nf++) {
            int nfg = nh * 12 + nf;
            uint2 Bv = *(const uint2*)((const char*)Bw +
                        ((kc * 24 + nfg) * 64 + g * 8 + tig * 2) * 4);
            mma_fp16(acc[0][nf], A[0][0].x, A[0][1].x, A[0][0].y, A[0][1].y, Bv.x, Bv.y);
            mma_fp16(acc[1][nf], A[1][0].x, A[1][1].x, A[1][0].y, A[1][1].y, Bv.x, Bv.y);
        }
    }

#pragma unroll
    for (int nf = 0; nf < 12; nf++) {
        float2 bb;
        if (nh == 0) bb = (nf < 8) ? *(const float2*)(bq + nf * 8 + tig * 2)
                                   : *(const float2*)(bv + (nf - 8) * 8 + tig * 2);
        else         bb = (nf < 8) ? *(const float2*)(bk + nf * 8 + tig * 2)
                                   : *(const float2*)(bv + 32 + (nf - 8) * 8 + tig * 2);
#pragma unroll
        for (int mf = 0; mf < 2; mf++) {
            acc[mf][nf][0] += bb.x; acc[mf][nf][1] += bb.y;
            acc[mf][nf][2] += bb.x; acc[mf][nf][3] += bb.y;
        }
    }

#pragma unroll
    for (int mf = 0; mf < 2; mf++) {
        float ss0 = 0.f, ss1 = 0.f;
#pragma unroll
        for (int nf = 0; nf < 8; nf++) {
            ss0 += acc[mf][nf][0] * acc[mf][nf][0] + acc[mf][nf][1] * acc[mf][nf][1];
            ss1 += acc[mf][nf][2] * acc[mf][nf][2] + acc[mf][nf][3] * acc[mf][nf][3];
        }
        ss0 += __shfl_xor_sync(0xffffffffu, ss0, 1);
        ss0 += __shfl_xor_sync(0xffffffffu, ss0, 2);
        ss1 += __shfl_xor_sync(0xffffffffu, ss1, 1);
        ss1 += __shfl_xor_sync(0xffffffffu, ss1, 2);
        float inv0 = rsqrtf(ss0), inv1 = rsqrtf(ss1);
        const int pxA = px0 + mf * 16 + g, pxB = pxA + 8;

        if (nh == 0) {
#pragma unroll
            for (int nf = 0; nf < 8; nf++) {
                int w = (nf >> 1) * 8 + tig * 2 + (nf & 1);
                qn[pxA * 33 + w] = h2pack(acc[mf][nf][0] * inv0, acc[mf][nf][1] * inv0);
                qn[pxB * 33 + w] = h2pack(acc[mf][nf][2] * inv1, acc[mf][nf][3] * inv1);
            }
        } else {
#pragma unroll
            for (int nf = 0; nf < 8; nf++) {
                int m = nf * 8 + tig * 2;
                knh[m * 136 + pxA]       = __float2half(acc[mf][nf][0] * inv0);
                knh[(m + 1) * 136 + pxA] = __float2half(acc[mf][nf][1] * inv0);
                knh[m * 136 + pxB]       = __float2half(acc[mf][nf][2] * inv1);
                knh[(m + 1) * 136 + pxB] = __float2half(acc[mf][nf][3] * inv1);
            }
        }
#pragma unroll
        for (int nf = 8; nf < 12; nf++) {
            int c = (nh ? 32 : 0) + (nf - 8) * 8 + tig * 2;
            vh[c * 136 + pxA]       = __float2half(acc[mf][nf][0]);
            vh[(c + 1) * 136 + pxA] = __float2half(acc[mf][nf][1]);
            vh[c * 136 + pxB]       = __float2half(acc[mf][nf][2]);
            vh[(c + 1) * 136 + pxB] = __float2half(acc[mf][nf][3]);
        }
    }
    __syncthreads();

    // Qn bulk copy to global (coalesced)
    {
        uint32_t* gq = g_QnP + (((size_t)b << 16) + n0) * 32;
        for (int j = tid; j < 4096; j += 256)
            gq[j] = qn[(j >> 5) * 33 + (j & 31)];
    }

    // ksum / vsum (fp16 row sums, 128 atomics per block)
    if (tid < 128) {
        const uint32_t* rw = (tid < 64)
            ? (const uint32_t*)(sm + QK_KN) + tid * 68
            : (const uint32_t*)(sm + QK_V) + (tid - 64) * 68;
        float s = 0.f;
#pragma unroll 8
        for (int j = 0; j < 64; j++) { float2 f = h2up(rw[j]); s += f.x + f.y; }
        float* dp = (tid < 64) ? &g_ksum[b * 64 + tid] : &g_vsum[b * 64 + tid - 64];
        atomicAdd(dp, s);
    }

    // aggkv[m][c] = sum_px Kn[m][px] V[c][px] via mma (K=128 px, 8 chunks)
    {
        const int mt = wid & 3, nh2 = wid >> 2;
        const uint32_t* knw = (const uint32_t*)(sm + QK_KN);
        const uint32_t* vw  = (const uint32_t*)(sm + QK_V);
        float ag[4][4];
#pragma unroll
        for (int nf = 0; nf < 4; nf++)
#pragma unroll
            for (int r = 0; r < 4; r++) ag[nf][r] = 0.f;

#pragma unroll
        for (int kc = 0; kc < 8; kc++) {
            int ra = (mt * 16 + g) * 68 + kc * 8 + tig;
            uint32_t a0 = knw[ra],          a2 = knw[ra + 4];
            uint32_t a1 = knw[ra + 8 * 68], a3 = knw[ra + 8 * 68 + 4];
#pragma unroll
            for (int nf = 0; nf < 4; nf++) {
                int rb = (nh2 * 32 + nf * 8 + g) * 68 + kc * 8 + tig;
                mma_fp16(ag[nf], a0, a1, a2, a3, vw[rb], vw[rb + 4]);
            }
        }

        // stage to smem (reuse xa region), then coalesced store to scratch
        float* agg_s = (float*)(sm + QK_XA);
#pragma unroll
        for (int nf = 0; nf < 4; nf++) {
            int r0 = (mt * 16 + g) * 66 + nh2 * 32 + nf * 8 + tig * 2;
            *(float2*)&agg_s[r0]          = make_float2(ag[nf][0], ag[nf][1]);
            *(float2*)&agg_s[r0 + 8 * 66] = make_float2(ag[nf][2], ag[nf][3]);
        }
        __syncthreads();
        float* gp = gpart + (size_t)blockIdx.x * 4096;
        for (int j = tid; j < 4096; j += 256)
            gp[j] = agg_s[(j >> 6) * 66 + (j & 63)];
    }
}

// ---------------------------------------------------------------------------
// reduce per-block aggkv partials: g_aggkv[b][idx] = sum over 512 blocks
__global__ void __launch_bounds__(256, 1)
k_red(const float* __restrict__ gpart) {
    int e = blockIdx.x * 256 + threadIdx.x;   // 0..32767
    int b = e >> 12, idx = e & 4095;
    const float* p = gpart + ((size_t)b * 512) * 4096 + idx;
    float s0 = 0.f, s1 = 0.f, s2 = 0.f, s3 = 0.f;
#pragma unroll 4
    for (int q = 0; q < 512; q += 4) {
        s0 += p[(size_t)q * 4096];
        s1 += p[(size_t)(q + 1) * 4096];
        s2 += p[(size_t)(q + 2) * 4096];
        s3 += p[(size_t)(q + 3) * 4096];
    }
    g_aggkv[e] = (s0 + s1) + (s2 + s3);
}

// ---------------------------------------------------------------------------
__global__ void __launch_bounds__(256, 1)
k_fin(const float* __restrict__ Wr) {
    __shared__ float a_s[4096];
    __shared__ float w_s[4096];
    __shared__ float vs_s[64];

    int b = blockIdx.x;
    int tid = threadIdx.x;

    for (int idx = tid; idx < 4096; idx += 256) {
        a_s[idx] = g_aggkv[b * 4096 + idx];
        int o = idx & 63, c = idx >> 6;
        w_s[c * 64 + o] = Wr[o * 64 + c];
    }
    if (tid < 64) vs_s[tid] = g_vsum[b * 64 + tid];
    __syncthreads();

    int o = tid & 63, mg = tid >> 6;
    if (mg == 0) {
        float s = 0.f;
#pragma unroll 8
        for (int c = 0; c < 64; c++) s += w_s[c * 64 + o] * vs_s[c];
        g_wrvs[b * 64 + o] = s;
    }
    int nf = o >> 3, gg = o & 7;
#pragma unroll 1
    for (int m = mg * 16; m < mg * 16 + 16; m += 2) {
        float t0 = 0.f, t1 = 0.f;
#pragma unroll 8
        for (int c = 0; c < 64; c++) {
            t0 += w_s[c * 64 + o] * a_s[m * 64 + c];
            t1 += w_s[c * 64 + o] * a_s[(m + 1) * 64 + c];
        }
        int kc = m >> 4, r = m & 15;
        int s2 = r >> 3, tg = (r & 7) >> 1;
        g_M2h[b * 2048 + ((kc * 8 + nf) * 64 + gg * 8 + tg * 2 + s2)] = h2pack(t0, t1);
    }
}

// ---------------------------------------------------------------------------
#define AT_QN   0
#define AT_M2   20480
#define AT_KS   28672
#define AT_WV   28928
#define AT_BR   29184
#define AT_SMEM 29440

__global__ void __launch_bounds__(256, 1)
k_attn(const float* __restrict__ br) {
    extern __shared__ char sm[];
    uint32_t* m2  = (uint32_t*)(sm + AT_M2);
    float*    ks  = (float*)(sm + AT_KS);
    float*    wv  = (float*)(sm + AT_WV);
    float*    brs = (float*)(sm + AT_BR);

    const int tid = threadIdx.x;
    const int b  = blockIdx.x >> 9;
    const int n0 = (blockIdx.x & 511) << 7;

    {
        const uint4* gq = (const uint4*)(g_QnP + (((size_t)b << 16) + n0) * 32);
        for (int i = tid; i < 1024; i += 256) {
            int px = i >> 3, q4 = i & 7;
            *(uint4*)(sm + (px * 40 + q4 * 4) * 4) = __ldg(gq + px * 8 + q4);
        }
    }
    for (int i = tid; i < 2048; i += 256) m2[i] = g_M2h[b * 2048 + i];
    if (tid < 64) {
        ks[tid]  = g_ksum[b * 64 + tid] + 1e-6f;
        wv[tid]  = g_wrvs[b * 64 + tid];
        brs[tid] = __ldg(&br[tid]);
    }
    __syncthreads();

    const int wid = tid >> 5, lane = tid & 31;
    const int g = lane >> 2, tig = lane & 3;
    const int px0 = wid << 4;

    float acc[8][4];
#pragma unroll
    for (int nf = 0; nf < 8; nf++)
#pragma unroll
        for (int r = 0; r < 4; r++) acc[nf][r] = 0.f;
    float dot0 = 0.f, dot1 = 0.f;

#pragma unroll
    for (int kc = 0; kc < 4; kc++) {
        const char* ab = sm + ((px0 + g) * 40 + tig * 2) * 4;
        uint2 A0 = *(const uint2*)(ab + kc * 32);
        uint2 A1 = *(const uint2*)(ab + 8 * 160 + kc * 32);
        float2 ka = *(const float2*)&ks[kc * 16 + tig * 2];
        float2 kb = *(const float2*)&ks[kc * 16 + tig * 2 + 8];
        float2 f;
        f = h2up(A0.x); dot0 += f.x * ka.x + f.y * ka.y;
        f = h2up(A0.y); dot0 += f.x * kb.x + f.y * kb.y;
        f = h2up(A1.x); dot1 += f.x * ka.x + f.y * ka.y;
        f = h2up(A1.y); dot1 += f.x * kb.x + f.y * kb.y;
#pragma unroll
        for (int nf = 0; nf < 8; nf++) {
            uint2 Bv = *(const uint2*)((const char*)m2 +
                        ((kc * 8 + nf) * 64 + g * 8 + tig * 2) * 4);
            mma_fp16(acc[nf], A0.x, A1.x, A0.y, A1.y, Bv.x, Bv.y);
        }
    }
    dot0 += __shfl_xor_sync(0xffffffffu, dot0, 1);
    dot0 += __shfl_xor_sync(0xffffffffu, dot0, 2);
    dot1 += __shfl_xor_sync(0xffffffffu, dot1, 1);
    dot1 += __shfl_xor_sync(0xffffffffu, dot1, 2);
    float den0 = 1.f / (65536.f + dot0);
    float den1 = 1.f / (65536.f + dot1);

    uint32_t* ga = g_attnP + (((size_t)b << 16) + n0) * 32;
#pragma unroll
    for (int nf = 0; nf < 8; nf++) {
        int o = nf * 8 + tig * 2;
        int w = (nf >> 1) * 8 + tig * 2 + (nf & 1);
        float v0 = brs[o]     + den0 * (wv[o]     + acc[nf][0]);
        float v1 = brs[o + 1] + den0 * (wv[o + 1] + acc[nf][1]);
        float v2 = brs[o]     + den1 * (wv[o]     + acc[nf][2]);
        float v3 = brs[o + 1] + den1 * (wv[o + 1] + acc[nf][3]);
        ga[(px0 + g) * 32 + w]     = h2pack(v0, v1);
        ga[(px0 + g + 8) * 32 + w] = h2pack(v2, v3);
    }
}

// ---------------------------------------------------------------------------
#define CB_OFF   256
#define CA_OFF   73984
#define CA_SLOT  20800
#define CV_SMEM  198784

__device__ __forceinline__ void cv_stage_row(char* smem, int slot,
                                             const uint4* __restrict__ src,
                                             int b, int gy, int x0, int tid) {
    char* dstc = smem + CA_OFF + slot * CA_SLOT;
    if ((unsigned)gy < 256u) {
        const uint4* sp = src + (((size_t)(b * 65536 + gy * 256)) << 3);
        for (int i = tid; i < 1040; i += 256) {
            int px = i >> 3, q4 = i & 7;
            int gx = x0 - 1 + px;
            uint4 v = make_uint4(0u, 0u, 0u, 0u);
            if ((unsigned)gx < 256u) v = __ldg(sp + (gx << 3) + q4);
            *(uint4*)(dstc + (px * 40 + q4 * 4) * 4) = v;
        }
    } else {
        for (int i = tid; i < 1040; i += 256) {
            int px = i >> 3, q4 = i & 7;
            *(uint4*)(dstc + (px * 40 + q4 * 4) * 4) = make_uint4(0u, 0u, 0u, 0u);
        }
    }
}

__global__ void __launch_bounds__(256, 1)
k_conv_mma(const uint4* __restrict__ srcP, const float* __restrict__ bias,
           float* __restrict__ dstF, uint32_t* __restrict__ dstP,
           const float* __restrict__ xres, int fuse, int convIdx) {
    extern __shared__ char smc[];
    const int tid = threadIdx.x;
    const int wid = tid >> 5;
    const int lane = tid & 31;
    const int g   = lane >> 2;
    const int tig = lane & 3;

    const int xh   = blockIdx.x & 1;
    const int band = (blockIdx.x >> 1) & 31;
    const int b    = blockIdx.x >> 6;
    const int y0   = band << 3;
    const int x0   = xh << 7;

    if (tid < 64) ((float*)smc)[tid] = bias[tid];
    {
        const uint4* bsrc = (const uint4*)(g_convB + convIdx * 18432);
        uint4* bdst = (uint4*)(smc + CB_OFF);
        for (int q = tid; q < 4608; q += 256) bdst[q] = bsrc[q];
    }

    cv_stage_row(smc, (y0)     % 6, srcP, b, y0 - 1, x0, tid);
    cv_stage_row(smc, (y0 + 1) % 6, srcP, b, y0,     x0, tid);
    cv_stage_row(smc, (y0 + 2) % 6, srcP, b, y0 + 1, x0, tid);
    cv_stage_row(smc, (y0 + 3) % 6, srcP, b, y0 + 2, x0, tid);
    __syncthreads();

    const int rsel = wid >> 2;
    const int px0  = (wid & 3) << 5;

    for (int t = 0; t < 8; t += 2) {
        const int y = y0 + t + rsel;

        float acc[16][4];
#pragma unroll
        for (int i = 0; i < 16; i++)
#pragma unroll
            for (int r = 0; r < 4; r++) acc[i][r] = 0.f;

#pragma unroll
        for (int ky = 0; ky < 3; ky++) {
            const char* aSlot = smc + CA_OFF + ((y + ky) % 6) * CA_SLOT;
#pragma unroll
            for (int kx = 0; kx < 3; kx++) {
                const char* aBase = aSlot + ((px0 + kx + g) * 40 + tig * 2) * 4;
                const char* bTap  = smc + CB_OFF + (ky * 3 + kx) * 8192
                                    + (g * 8 + tig * 2) * 4;
#pragma unroll
                for (int kc = 0; kc < 4; kc++) {
                    uint2 A0 = *(const uint2*)(aBase + kc * 32);
                    uint2 A1 = *(const uint2*)(aBase + 8  * 160 + kc * 32);
                    uint2 A2 = *(const uint2*)(aBase + 16 * 160 + kc * 32);
                    uint2 A3 = *(const uint2*)(aBase + 24 * 160 + kc * 32);
                    const char* bc = bTap + kc * 2048;
#pragma unroll
                    for (int nf = 0; nf < 8; nf++) {
                        uint2 B = *(const uint2*)(bc + nf * 256);
                        mma_fp16(acc[nf],     A0.x, A1.x, A0.y, A1.y, B.x, B.y);
                        mma_fp16(acc[8 + nf], A2.x, A3.x, A2.y, A3.y, B.x, B.y);
                    }
                }
            }
        }

        {
            const float* bs = (const float*)smc;
            const int pxb = x0 + px0 + g;
            if (fuse) {
                const size_t rowOff = ((size_t)b << 22) + ((size_t)y << 8);
#pragma unroll
                for (int nf = 0; nf < 8; nf++) {
                    int o0 = nf * 8 + tig * 2;
                    float b0v = bs[o0], b1v = bs[o0 + 1];
#pragma unroll
                    for (int mf = 0; mf < 2; mf++) {
                        int pxl = pxb + mf * 16;
                        size_t i00 = rowOff + ((size_t)o0 << 16) + pxl;
                        size_t i01 = rowOff + ((size_t)(o0 + 1) << 16) + pxl;
                        float v00 = acc[mf * 8 + nf][0] + b0v;
                        float v01 = acc[mf * 8 + nf][1] + b1v;
                        float v10 = acc[mf * 8 + nf][2] + b0v;
                        float v11 = acc[mf * 8 + nf][3] + b1v;
                        float xa = xres[i00],     xb2 = xres[i01];
                        float xc = xres[i00 + 8], xd = xres[i01 + 8];
                        dstF[i00]     = v00 * xa + xa;
                        dstF[i01]     = v01 * xb2 + xb2;
                        dstF[i00 + 8] = v10 * xc + xc;
                        dstF[i01 + 8] = v11 * xd + xd;
                    }
                }
            } else {
                const size_t rowBase = ((size_t)(b * 65536 + y * 256));
#pragma unroll
                for (int nf = 0; nf < 8; nf++) {
                    int o0 = nf * 8 + tig * 2;
                    float b0v = bs[o0], b1v = bs[o0 + 1];
                    int w = (nf >> 1) * 8 + tig * 2 + (nf & 1);
#pragma unroll
                    for (int mf = 0; mf < 2; mf++) {
                        int pxl = pxb + mf * 16;
                        size_t base = (rowBase + pxl) * 32 + w;
                        dstP[base]          = h2pack(acc[mf * 8 + nf][0] + b0v,
                                                     acc[mf * 8 + nf][1] + b1v);
                        dstP[base + 8 * 32] = h2pack(acc[mf * 8 + nf][2] + b0v,
                                                     acc[mf * 8 + nf][3] + b1v);
                    }
                }
            }
        }

        if (t < 6) {
            cv_stage_row(smc, (y0 + t + 4) % 6, srcP, b, y0 + t + 3, x0, tid);
            cv_stage_row(smc, (y0 + t + 5) % 6, srcP, b, y0 + t + 4, x0, tid);
        }
        __syncthreads();
    }
}

// ---------------------------------------------------------------------------
extern "C" void kernel_launch(void* const* d_in, const int* in_sizes, int n_in,
                              void* d_out, int out_size) {
    const float* x  = (const float*)d_in[0];
    const float* Wq = (const float*)d_in[1];
    const float* bq = (const float*)d_in[2];
    const float* Wk = (const float*)d_in[3];
    const float* bk = (const float*)d_in[4];
    const float* Wv = (const float*)d_in[5];
    const float* bv = (const float*)d_in[6];
    const float* Wr = (const float*)d_in[7];
    const float* br = (const float*)d_in[8];
    const float* W1 = (const float*)d_in[9];
    const float* b1 = (const float*)d_in[10];
    const float* W2 = (const float*)d_in[11];
    const float* b2 = (const float*)d_in[12];
    float* out = (float*)d_out;

    cudaFuncSetAttribute(k_qkv,      cudaFuncAttributeMaxDynamicSharedMemorySize, QK_SMEM);
    cudaFuncSetAttribute(k_attn,     cudaFuncAttributeMaxDynamicSharedMemorySize, AT_SMEM);
    cudaFuncSetAttribute(k_conv_mma, cudaFuncAttributeMaxDynamicSharedMemorySize, CV_SMEM);

    void *p_attnP, *p_t1P;
    cudaGetSymbolAddress(&p_attnP, g_attnP);
    cudaGetSymbolAddress(&p_t1P, g_t1P);

    k_prep<<<170, 256>>>(Wq, Wk, Wv, W1, W2);
    k_qkv<<<4096, 256, QK_SMEM>>>(x, bq, bk, bv, (float*)p_t1P);
    k_red<<<128, 256>>>((const float*)p_t1P);
    k_fin<<<8, 256>>>(Wr);
    k_attn<<<4096, 256, AT_SMEM>>>(br);
    k_conv_mma<<<512, 256, CV_SMEM>>>((const uint4*)p_attnP, b1, nullptr,
                                      (uint32_t*)p_t1P, nullptr, 0, 0);
    k_conv_mma<<<512, 256, CV_SMEM>>>((const uint4*)p_t1P, b2, out,
                                      nullptr, x, 1, 1);
}

// round 8
// speedup vs baseline: 5.3630x; 1.1324x over previous
#include <cuda_runtime.h>
#include <cuda_fp16.h>
#include <cstdint>

// ---------------------------------------------------------------------------
// HydraAttention_v2 — fully tensorized (mma.sync fp16 m16n8k16), fp16 packed
// fragment-layout intermediates. Convs re-tiled (64px x 32out) for occ=2.
// B=8, C=64, H=W=256, N=65536
// ---------------------------------------------------------------------------

#define BATCH 8
#define CH    64
#define NPIX  65536

typedef unsigned long long ull;

__device__ uint32_t g_QnP[BATCH * NPIX * 32];    // packed fp16 Qn
__device__ uint32_t g_attnP[BATCH * NPIX * 32];  // packed fp16 attn
__device__ uint32_t g_t1P[BATCH * NPIX * 32];    // conv1 out; BEFORE conv1: qkv aggkv scratch
__device__ float    g_ksum[BATCH * CH];
__device__ float    g_vsum[BATCH * CH];
__device__ float    g_aggkv[BATCH * CH * CH];
__device__ float    g_wrvs[BATCH * CH];
__device__ uint32_t g_M2h[BATCH * 2048];         // packed fp16 M2 B-frags
__device__ uint32_t g_qkvB[6144];                // packed fp16 QKV weights
__device__ uint32_t g_convB[2 * 36 * 64 * 8];    // packed fp16 conv weights

// ---- helpers ----------------------------------------------------------------
__device__ __forceinline__ void mma_fp16(float c[4], uint32_t a0, uint32_t a1,
                                         uint32_t a2, uint32_t a3,
                                         uint32_t b0, uint32_t b1) {
    asm volatile(
        "mma.sync.aligned.m16n8k16.row.col.f32.f16.f16.f32 "
        "{%0,%1,%2,%3}, {%4,%5,%6,%7}, {%8,%9}, {%0,%1,%2,%3};"
        : "+f"(c[0]), "+f"(c[1]), "+f"(c[2]), "+f"(c[3])
        : "r"(a0), "r"(a1), "r"(a2), "r"(a3), "r"(b0), "r"(b1));
}
__device__ __forceinline__ uint32_t h2pack(float a, float b) {
    __half2 h = __float22half2_rn(make_float2(a, b));
    return *(uint32_t*)&h;
}
__device__ __forceinline__ float2 h2up(uint32_t w) {
    __half2 h = *(__half2*)&w;
    return __half22float2(h);
}

// ---------------------------------------------------------------------------
__global__ void k_prep(const float* __restrict__ Wq, const float* __restrict__ Wk,
                       const float* __restrict__ Wv,
                       const float* __restrict__ W1, const float* __restrict__ W2) {
    int i = blockIdx.x * 256 + threadIdx.x;
    if (i < 36864) {
        int f = i;
        int conv = f / 18432;
        int r    = f % 18432;
        int chunk = r >> 9;
        int w     = r & 511;
        int n   = w >> 3;
        int ww  = w & 7;
        int tig = ww >> 1, s = ww & 1;
        int tap = chunk >> 2, kc = chunk & 3;
        int ch = kc * 16 + 2 * tig + 8 * s;
        const float* W = conv ? W2 : W1;
        g_convB[f] = h2pack(W[n * 576 + ch * 9 + tap], W[n * 576 + (ch + 1) * 9 + tap]);
    } else if (i < 43008) {
        int f = i - 36864;
        int s = f & 1, tig = (f >> 1) & 3, g = (f >> 3) & 7;
        int nf = (f >> 6) % 24, kc = f / (64 * 24);
        int n = nf * 8 + g;
        int ch = kc * 16 + tig * 2 + s * 8;
        const float* W; int row;
        if (n < 64)       { W = Wq; row = n; }
        else if (n < 96)  { W = Wv; row = n - 64; }
        else if (n < 160) { W = Wk; row = n - 96; }
        else              { W = Wv; row = n - 128; }
        g_qkvB[f] = h2pack(W[row * 64 + ch], W[row * 64 + ch + 1]);
    } else if (i < 43520) {
        int j = i - 43008;
        g_ksum[j] = 0.f; g_vsum[j] = 0.f;
    }
}

// ---------------------------------------------------------------------------
// k_qkv: 128-px blocks. QKV GEMM via mma; norms; Qn packed out; Kn/V to fp16
// smem; aggkv 64x64x128 GEMM via mma -> per-block partial to scratch (g_t1P).
#define QK_XA   0            // 20480 (x frags; reused as agg staging 64*66*4)
#define QK_B    20480        // 24576
#define QK_KN   45056        // 64*68 words = 17408 B (fp16 [m][px], stride 68 w)
#define QK_V    62464        // 17408
#define QK_QN   79872        // 128*33*4 = 16896
#define QK_SMEM 96768

__global__ void __launch_bounds__(256, 2)
k_qkv(const float* __restrict__ x, const float* __restrict__ bq,
      const float* __restrict__ bk, const float* __restrict__ bv,
      float* __restrict__ gpart) {
    extern __shared__ char sm[];
    uint32_t* Bw  = (uint32_t*)(sm + QK_B);
    __half*   knh = (__half*)(sm + QK_KN);
    __half*   vh  = (__half*)(sm + QK_V);
    uint32_t* qn  = (uint32_t*)(sm + QK_QN);

    const int tid = threadIdx.x;
    const int b  = blockIdx.x >> 9;
    const int n0 = (blockIdx.x & 511) << 7;

    for (int i = tid; i < 6144; i += 256) Bw[i] = g_qkvB[i];

    const float* xb = x + ((size_t)b << 22) + n0;
    {
        uint32_t* xa = (uint32_t*)(sm + QK_XA);
        for (int i = tid; i < 4096; i += 256) {
            int px = i & 127, p = i >> 7;
            float f0 = __ldg(xb + ((size_t)(2 * p) << 16) + px);
            float f1 = __ldg(xb + ((size_t)(2 * p + 1) << 16) + px);
            int kc = p >> 3, t3 = p & 7;
            int w = kc * 8 + (t3 & 3) * 2 + (t3 >> 2);
            xa[px * 40 + w] = h2pack(f0, f1);
        }
    }
    __syncthreads();

    const int wid = tid >> 5, lane = tid & 31;
    const int g = lane >> 2, tig = lane & 3;
    const int pxq = wid & 3, nh = wid >> 2;
    const int px0 = pxq << 5;

    float acc[2][12][4];
#pragma unroll
    for (int mf = 0; mf < 2; mf++)
#pragma unroll
        for (int nf = 0; nf < 12; nf++)
#pragma unroll
            for (int r = 0; r < 4; r++) acc[mf][nf][r] = 0.f;

#pragma unroll
    for (int kc = 0; kc < 4; kc++) {
        uint2 A[2][2];
#pragma unroll
        for (int mf = 0; mf < 2; mf++) {
            const char* ab = sm + QK_XA + ((px0 + mf * 16 + g) * 40 + tig * 2) * 4;
            A[mf][0] = *(const uint2*)(ab + kc * 32);
            A[mf][1] = *(const uint2*)(ab + 8 * 160 + kc * 32);
        }
#pragma unroll
        for (int nf = 0; nf < 12; nf++) {
            int nfg = nh * 12 + nf;
            uint2 Bv = *(const uint2*)((const char*)Bw +
                        ((kc * 24 + nfg) * 64 + g * 8 + tig * 2) * 4);
            mma_fp16(acc[0][nf], A[0][0].x, A[0][1].x, A[0][0].y, A[0][1].y, Bv.x, Bv.y);
            mma_fp16(acc[1][nf], A[1][0].x, A[1][1].x, A[1][0].y, A[1][1].y, Bv.x, Bv.y);
        }
    }

#pragma unroll
    for (int nf = 0; nf < 12; nf++) {
        float2 bb;
        if (nh == 0) bb = (nf < 8) ? *(const float2*)(bq + nf * 8 + tig * 2)
                                   : *(const float2*)(bv + (nf - 8) * 8 + tig * 2);
        else         bb = (nf < 8) ? *(const float2*)(bk + nf * 8 + tig * 2)
                                   : *(const float2*)(bv + 32 + (nf - 8) * 8 + tig * 2);
#pragma unroll
        for (int mf = 0; mf < 2; mf++) {
            acc[mf][nf][0] += bb.x; acc[mf][nf][1] += bb.y;
            acc[mf][nf][2] += bb.x; acc[mf][nf][3] += bb.y;
        }
    }

#pragma unroll
    for (int mf = 0; mf < 2; mf++) {
        float ss0 = 0.f, ss1 = 0.f;
#pragma unroll
        for (int nf = 0; nf < 8; nf++) {
            ss0 += acc[mf][nf][0] * acc[mf][nf][0] + acc[mf][nf][1] * acc[mf][nf][1];
            ss1 += acc[mf][nf][2] * acc[mf][nf][2] + acc[mf][nf][3] * acc[mf][nf][3];
        }
        ss0 += __shfl_xor_sync(0xffffffffu, ss0, 1);
        ss0 += __shfl_xor_sync(0xffffffffu, ss0, 2);
        ss1 += __shfl_xor_sync(0xffffffffu, ss1, 1);
        ss1 += __shfl_xor_sync(0xffffffffu, ss1, 2);
        float inv0 = rsqrtf(ss0), inv1 = rsqrtf(ss1);
        const int pxA = px0 + mf * 16 + g, pxB = pxA + 8;

        if (nh == 0) {
#pragma unroll
            for (int nf = 0; nf < 8; nf++) {
                int w = (nf >> 1) * 8 + tig * 2 + (nf & 1);
                qn[pxA * 33 + w] = h2pack(acc[mf][nf][0] * inv0, acc[mf][nf][1] * inv0);
                qn[pxB * 33 + w] = h2pack(acc[mf][nf][2] * inv1, acc[mf][nf][3] * inv1);
            }
        } else {
#pragma unroll
            for (int nf = 0; nf < 8; nf++) {
                int m = nf * 8 + tig * 2;
                knh[m * 136 + pxA]       = __float2half(acc[mf][nf][0] * inv0);
                knh[(m + 1) * 136 + pxA] = __float2half(acc[mf][nf][1] * inv0);
                knh[m * 136 + pxB]       = __float2half(acc[mf][nf][2] * inv1);
                knh[(m + 1) * 136 + pxB] = __float2half(acc[mf][nf][3] * inv1);
            }
        }
#pragma unroll
        for (int nf = 8; nf < 12; nf++) {
            int c = (nh ? 32 : 0) + (nf - 8) * 8 + tig * 2;
            vh[c * 136 + pxA]       = __float2half(acc[mf][nf][0]);
            vh[(c + 1) * 136 + pxA] = __float2half(acc[mf][nf][1]);
            vh[c * 136 + pxB]       = __float2half(acc[mf][nf][2]);
            vh[(c + 1) * 136 + pxB] = __float2half(acc[mf][nf][3]);
        }
    }
    __syncthreads();

    // Qn bulk copy to global (coalesced)
    {
        uint32_t* gq = g_QnP + (((size_t)b << 16) + n0) * 32;
        for (int j = tid; j < 4096; j += 256)
            gq[j] = qn[(j >> 5) * 33 + (j & 31)];
    }

    // ksum / vsum (fp16 row sums, 128 atomics per block)
    if (tid < 128) {
        const uint32_t* rw = (tid < 64)
            ? (const uint32_t*)(sm + QK_KN) + tid * 68
            : (const uint32_t*)(sm + QK_V) + (tid - 64) * 68;
        float s = 0.f;
#pragma unroll 8
        for (int j = 0; j < 64; j++) { float2 f = h2up(rw[j]); s += f.x + f.y; }
        float* dp = (tid < 64) ? &g_ksum[b * 64 + tid] : &g_vsum[b * 64 + tid - 64];
        atomicAdd(dp, s);
    }

    // aggkv[m][c] = sum_px Kn[m][px] V[c][px] via mma (K=128 px, 8 chunks)
    {
        const int mt = wid & 3, nh2 = wid >> 2;
        const uint32_t* knw = (const uint32_t*)(sm + QK_KN);
        const uint32_t* vw  = (const uint32_t*)(sm + QK_V);
        float ag[4][4];
#pragma unroll
        for (int nf = 0; nf < 4; nf++)
#pragma unroll
            for (int r = 0; r < 4; r++) ag[nf][r] = 0.f;

#pragma unroll
        for (int kc = 0; kc < 8; kc++) {
            int ra = (mt * 16 + g) * 68 + kc * 8 + tig;
            uint32_t a0 = knw[ra],          a2 = knw[ra + 4];
            uint32_t a1 = knw[ra + 8 * 68], a3 = knw[ra + 8 * 68 + 4];
#pragma unroll
            for (int nf = 0; nf < 4; nf++) {
                int rb = (nh2 * 32 + nf * 8 + g) * 68 + kc * 8 + tig;
                mma_fp16(ag[nf], a0, a1, a2, a3, vw[rb], vw[rb + 4]);
            }
        }

        float* agg_s = (float*)(sm + QK_XA);
#pragma unroll
        for (int nf = 0; nf < 4; nf++) {
            int r0 = (mt * 16 + g) * 66 + nh2 * 32 + nf * 8 + tig * 2;
            *(float2*)&agg_s[r0]          = make_float2(ag[nf][0], ag[nf][1]);
            *(float2*)&agg_s[r0 + 8 * 66] = make_float2(ag[nf][2], ag[nf][3]);
        }
        __syncthreads();
        float* gp = gpart + (size_t)blockIdx.x * 4096;
        for (int j = tid; j < 4096; j += 256)
            gp[j] = agg_s[(j >> 6) * 66 + (j & 63)];
    }
}

// ---------------------------------------------------------------------------
// reduce per-block aggkv partials: g_aggkv[b][idx] = sum over 512 blocks
__global__ void __launch_bounds__(256, 1)
k_red(const float* __restrict__ gpart) {
    int e = blockIdx.x * 256 + threadIdx.x;   // 0..32767
    int b = e >> 12, idx = e & 4095;
    const float* p = gpart + ((size_t)b * 512) * 4096 + idx;
    float s0 = 0.f, s1 = 0.f, s2 = 0.f, s3 = 0.f;
#pragma unroll 4
    for (int q = 0; q < 512; q += 4) {
        s0 += p[(size_t)q * 4096];
        s1 += p[(size_t)(q + 1) * 4096];
        s2 += p[(size_t)(q + 2) * 4096];
        s3 += p[(size_t)(q + 3) * 4096];
    }
    g_aggkv[e] = (s0 + s1) + (s2 + s3);
}

// ---------------------------------------------------------------------------
// k_fin: grid 32 (b x m-quarter). wrvs + M2 -> packed fp16
__global__ void __launch_bounds__(256, 1)
k_fin(const float* __restrict__ Wr) {
    __shared__ float a_s[1024];
    __shared__ float w_s[4096];
    __shared__ float vs_s[64];

    int b  = blockIdx.x >> 2;
    int mq = blockIdx.x & 3;
    int tid = threadIdx.x;

    for (int idx = tid; idx < 4096; idx += 256) {
        int o = idx & 63, c = idx >> 6;
        w_s[c * 64 + o] = Wr[o * 64 + c];
    }
    for (int idx = tid; idx < 1024; idx += 256)
        a_s[idx] = g_aggkv[b * 4096 + mq * 1024 + idx];
    if (tid < 64) vs_s[tid] = g_vsum[b * 64 + tid];
    __syncthreads();

    int o = tid & 63, sub = tid >> 6;
    if (mq == 0 && sub == 0) {
        float s = 0.f;
#pragma unroll 8
        for (int c = 0; c < 64; c++) s += w_s[c * 64 + o] * vs_s[c];
        g_wrvs[b * 64 + o] = s;
    }
    int nf = o >> 3, gg = o & 7;
#pragma unroll
    for (int ml = sub * 4; ml < sub * 4 + 4; ml += 2) {
        int m = mq * 16 + ml;
        float t0 = 0.f, t1 = 0.f;
#pragma unroll 8
        for (int c = 0; c < 64; c++) {
            t0 += w_s[c * 64 + o] * a_s[ml * 64 + c];
            t1 += w_s[c * 64 + o] * a_s[(ml + 1) * 64 + c];
        }
        int kc = m >> 4, r = m & 15;
        int s2 = r >> 3, tg = (r & 7) >> 1;
        g_M2h[b * 2048 + ((kc * 8 + nf) * 64 + gg * 8 + tg * 2 + s2)] = h2pack(t0, t1);
    }
}

// ---------------------------------------------------------------------------
#define AT_QN   0
#define AT_M2   20480
#define AT_KS   28672
#define AT_WV   28928
#define AT_BR   29184
#define AT_SMEM 29440

__global__ void __launch_bounds__(256, 1)
k_attn(const float* __restrict__ br) {
    extern __shared__ char sm[];
    uint32_t* m2  = (uint32_t*)(sm + AT_M2);
    float*    ks  = (float*)(sm + AT_KS);
    float*    wv  = (float*)(sm + AT_WV);
    float*    brs = (float*)(sm + AT_BR);

    const int tid = threadIdx.x;
    const int b  = blockIdx.x >> 9;
    const int n0 = (blockIdx.x & 511) << 7;

    {
        const uint4* gq = (const uint4*)(g_QnP + (((size_t)b << 16) + n0) * 32);
        for (int i = tid; i < 1024; i += 256) {
            int px = i >> 3, q4 = i & 7;
            *(uint4*)(sm + (px * 40 + q4 * 4) * 4) = __ldg(gq + px * 8 + q4);
        }
    }
    for (int i = tid; i < 2048; i += 256) m2[i] = g_M2h[b * 2048 + i];
    if (tid < 64) {
        ks[tid]  = g_ksum[b * 64 + tid] + 1e-6f;
        wv[tid]  = g_wrvs[b * 64 + tid];
        brs[tid] = __ldg(&br[tid]);
    }
    __syncthreads();

    const int wid = tid >> 5, lane = tid & 31;
    const int g = lane >> 2, tig = lane & 3;
    const int px0 = wid << 4;

    float acc[8][4];
#pragma unroll
    for (int nf = 0; nf < 8; nf++)
#pragma unroll
        for (int r = 0; r < 4; r++) acc[nf][r] = 0.f;
    float dot0 = 0.f, dot1 = 0.f;

#pragma unroll
    for (int kc = 0; kc < 4; kc++) {
        const char* ab = sm + ((px0 + g) * 40 + tig * 2) * 4;
        uint2 A0 = *(const uint2*)(ab + kc * 32);
        uint2 A1 = *(const uint2*)(ab + 8 * 160 + kc * 32);
        float2 ka = *(const float2*)&ks[kc * 16 + tig * 2];
        float2 kb = *(const float2*)&ks[kc * 16 + tig * 2 + 8];
        float2 f;
        f = h2up(A0.x); dot0 += f.x * ka.x + f.y * ka.y;
        f = h2up(A0.y); dot0 += f.x * kb.x + f.y * kb.y;
        f = h2up(A1.x); dot1 += f.x * ka.x + f.y * ka.y;
        f = h2up(A1.y); dot1 += f.x * kb.x + f.y * kb.y;
#pragma unroll
        for (int nf = 0; nf < 8; nf++) {
            uint2 Bv = *(const uint2*)((const char*)m2 +
                        ((kc * 8 + nf) * 64 + g * 8 + tig * 2) * 4);
            mma_fp16(acc[nf], A0.x, A1.x, A0.y, A1.y, Bv.x, Bv.y);
        }
    }
    dot0 += __shfl_xor_sync(0xffffffffu, dot0, 1);
    dot0 += __shfl_xor_sync(0xffffffffu, dot0, 2);
    dot1 += __shfl_xor_sync(0xffffffffu, dot1, 1);
    dot1 += __shfl_xor_sync(0xffffffffu, dot1, 2);
    float den0 = 1.f / (65536.f + dot0);
    float den1 = 1.f / (65536.f + dot1);

    uint32_t* ga = g_attnP + (((size_t)b << 16) + n0) * 32;
#pragma unroll
    for (int nf = 0; nf < 8; nf++) {
        int o = nf * 8 + tig * 2;
        int w = (nf >> 1) * 8 + tig * 2 + (nf & 1);
        float v0 = brs[o]     + den0 * (wv[o]     + acc[nf][0]);
        float v1 = brs[o + 1] + den0 * (wv[o + 1] + acc[nf][1]);
        float v2 = brs[o]     + den1 * (wv[o]     + acc[nf][2]);
        float v3 = brs[o + 1] + den1 * (wv[o + 1] + acc[nf][3]);
        ga[(px0 + g) * 32 + w]     = h2pack(v0, v1);
        ga[(px0 + g + 8) * 32 + w] = h2pack(v2, v3);
    }
}

// ---------------------------------------------------------------------------
// conv3x3 via mma.sync fp16, occ 2. Block: 64-px x-quarter x 32-out half x
// 8-row band. A ring: 6 slots of 66-px rows; B: this half's 36 chunks.
#define CB_OFF   256
#define CA_OFF   37120
#define CA_SLOT  10560
#define CV_SMEM  100480

__device__ __forceinline__ void cv_stage_row(char* smem, int slot,
                                             const uint4* __restrict__ src,
                                             int b, int gy, int x0, int tid) {
    char* dstc = smem + CA_OFF + slot * CA_SLOT;
    if ((unsigned)gy < 256u) {
        const uint4* sp = src + (((size_t)(b * 65536 + gy * 256)) << 3);
        for (int i = tid; i < 528; i += 256) {
            int px = i >> 3, q4 = i & 7;
            int gx = x0 - 1 + px;
            uint4 v = make_uint4(0u, 0u, 0u, 0u);
            if ((unsigned)gx < 256u) v = __ldg(sp + (gx << 3) + q4);
            *(uint4*)(dstc + (px * 40 + q4 * 4) * 4) = v;
        }
    } else {
        for (int i = tid; i < 528; i += 256) {
            int px = i >> 3, q4 = i & 7;
            *(uint4*)(dstc + (px * 40 + q4 * 4) * 4) = make_uint4(0u, 0u, 0u, 0u);
        }
    }
}

__global__ void __launch_bounds__(256, 2)
k_conv_mma(const uint4* __restrict__ srcP, const float* __restrict__ bias,
           float* __restrict__ dstF, uint32_t* __restrict__ dstP,
           const float* __restrict__ xres, int fuse, int convIdx) {
    extern __shared__ char smc[];
    const int tid = threadIdx.x;
    const int wid = tid >> 5;
    const int lane = tid & 31;
    const int g   = lane >> 2;
    const int tig = lane & 3;

    const int nh   = blockIdx.x & 1;
    const int xq   = (blockIdx.x >> 1) & 3;
    const int band = (blockIdx.x >> 3) & 31;
    const int b    = blockIdx.x >> 8;
    const int y0   = band << 3;
    const int x0   = xq << 6;

    if (tid < 64) ((float*)smc)[tid] = bias[tid];
    {
        const uint4* bsrc = (const uint4*)(g_convB + convIdx * 18432);
        uint4* bdst = (uint4*)(smc + CB_OFF);
        for (int q = tid; q < 2304; q += 256) {
            int c = q >> 6, j = q & 63;
            bdst[q] = bsrc[c * 128 + nh * 64 + j];
        }
    }

    cv_stage_row(smc, (y0)     % 6, srcP, b, y0 - 1, x0, tid);
    cv_stage_row(smc, (y0 + 1) % 6, srcP, b, y0,     x0, tid);
    cv_stage_row(smc, (y0 + 2) % 6, srcP, b, y0 + 1, x0, tid);
    cv_stage_row(smc, (y0 + 3) % 6, srcP, b, y0 + 2, x0, tid);
    __syncthreads();

    const int rsel = wid >> 2;
    const int px0  = (wid & 3) << 4;

    for (int t = 0; t < 8; t += 2) {
        const int y = y0 + t + rsel;

        float acc[4][4];
#pragma unroll
        for (int i = 0; i < 4; i++)
#pragma unroll
            for (int r = 0; r < 4; r++) acc[i][r] = 0.f;

#pragma unroll
        for (int ky = 0; ky < 3; ky++) {
            const char* aSlot = smc + CA_OFF + ((y + ky) % 6) * CA_SLOT;
#pragma unroll
            for (int kx = 0; kx < 3; kx++) {
                const char* aBase = aSlot + ((px0 + kx + g) * 40 + tig * 2) * 4;
                const char* bTap  = smc + CB_OFF + (ky * 3 + kx) * 4096
                                    + (g * 8 + tig * 2) * 4;
#pragma unroll
                for (int kc = 0; kc < 4; kc++) {
                    uint2 A0 = *(const uint2*)(aBase + kc * 32);
                    uint2 A1 = *(const uint2*)(aBase + 8 * 160 + kc * 32);
                    const char* bc = bTap + kc * 1024;
#pragma unroll
                    for (int nf = 0; nf < 4; nf++) {
                        uint2 B = *(const uint2*)(bc + nf * 256);
                        mma_fp16(acc[nf], A0.x, A1.x, A0.y, A1.y, B.x, B.y);
                    }
                }
            }
        }

        {
            const float* bs = (const float*)smc;
            const int pxA = x0 + px0 + g;
            const int pxB = pxA + 8;
            if (fuse) {
                const size_t rowOff = ((size_t)b << 22) + ((size_t)y << 8);
#pragma unroll
                for (int nf = 0; nf < 4; nf++) {
                    int o0 = nh * 32 + nf * 8 + tig * 2;
                    float b0v = bs[o0], b1v = bs[o0 + 1];
                    size_t i00 = rowOff + ((size_t)o0 << 16) + pxA;
                    size_t i01 = rowOff + ((size_t)(o0 + 1) << 16) + pxA;
                    size_t i10 = rowOff + ((size_t)o0 << 16) + pxB;
                    size_t i11 = rowOff + ((size_t)(o0 + 1) << 16) + pxB;
                    float v00 = acc[nf][0] + b0v;
                    float v01 = acc[nf][1] + b1v;
                    float v10 = acc[nf][2] + b0v;
                    float v11 = acc[nf][3] + b1v;
                    float xa = xres[i00], xb2 = xres[i01];
                    float xc = xres[i10], xd = xres[i11];
                    dstF[i00] = v00 * xa + xa;
                    dstF[i01] = v01 * xb2 + xb2;
                    dstF[i10] = v10 * xc + xc;
                    dstF[i11] = v11 * xd + xd;
                }
            } else {
                const size_t rowBase = ((size_t)(b * 65536 + y * 256));
#pragma unroll
                for (int nf = 0; nf < 4; nf++) {
                    int nfg = nh * 4 + nf;
                    int o0 = nfg * 8 + tig * 2;
                    float b0v = bs[o0], b1v = bs[o0 + 1];
                    int w = (nfg >> 1) * 8 + tig * 2 + (nfg & 1);
                    size_t baseA = (rowBase + pxA) * 32 + w;
                    size_t baseB = (rowBase + pxB) * 32 + w;
                    dstP[baseA] = h2pack(acc[nf][0] + b0v, acc[nf][1] + b1v);
                    dstP[baseB] = h2pack(acc[nf][2] + b0v, acc[nf][3] + b1v);
                }
            }
        }

        if (t < 6) {
            cv_stage_row(smc, (y0 + t + 4) % 6, srcP, b, y0 + t + 3, x0, tid);
            cv_stage_row(smc, (y0 + t + 5) % 6, srcP, b, y0 + t + 4, x0, tid);
        }
        __syncthreads();
    }
}

// ---------------------------------------------------------------------------
extern "C" void kernel_launch(void* const* d_in, const int* in_sizes, int n_in,
                              void* d_out, int out_size) {
    const float* x  = (const float*)d_in[0];
    const float* Wq = (const float*)d_in[1];
    const float* bq = (const float*)d_in[2];
    const float* Wk = (const float*)d_in[3];
    const float* bk = (const float*)d_in[4];
    const float* Wv = (const float*)d_in[5];
    const float* bv = (const float*)d_in[6];
    const float* Wr = (const float*)d_in[7];
    const float* br = (const float*)d_in[8];
    const float* W1 = (const float*)d_in[9];
    const float* b1 = (const float*)d_in[10];
    const float* W2 = (const float*)d_in[11];
    const float* b2 = (const float*)d_in[12];
    float* out = (float*)d_out;

    cudaFuncSetAttribute(k_qkv,      cudaFuncAttributeMaxDynamicSharedMemorySize, QK_SMEM);
    cudaFuncSetAttribute(k_attn,     cudaFuncAttributeMaxDynamicSharedMemorySize, AT_SMEM);
    cudaFuncSetAttribute(k_conv_mma, cudaFuncAttributeMaxDynamicSharedMemorySize, CV_SMEM);

    void *p_attnP, *p_t1P;
    cudaGetSymbolAddress(&p_attnP, g_attnP);
    cudaGetSymbolAddress(&p_t1P, g_t1P);

    k_prep<<<170, 256>>>(Wq, Wk, Wv, W1, W2);
    k_qkv<<<4096, 256, QK_SMEM>>>(x, bq, bk, bv, (float*)p_t1P);
    k_red<<<128, 256>>>((const float*)p_t1P);
    k_fin<<<32, 256>>>(Wr);
    k_attn<<<4096, 256, AT_SMEM>>>(br);
    k_conv_mma<<<2048, 256, CV_SMEM>>>((const uint4*)p_attnP, b1, nullptr,
                                       (uint32_t*)p_t1P, nullptr, 0, 0);
    k_conv_mma<<<2048, 256, CV_SMEM>>>((const uint4*)p_t1P, b2, out,
                                       nullptr, x, 1, 1);
}